// round 9
// baseline (speedup 1.0000x reference)
#include <cuda_runtime.h>
#include <cuda_fp16.h>
#include <cstdint>

#define NN   65536
#define INC  512
#define HD   1024
#define DIM  256

// quantization scales
#define S_X   24.f
#define S_WV  2873.f
#define S_V   40.f
#define S_K   127.f

// ---------------- scratch (device globals) -----------------------------------
__device__ __half  g_xh[NN * INC];               // x f16 (q,k GEMMs)
__device__ int8_t  g_x8[NN * INC];               // x s8 (v GEMM), x24
__device__ __half  g_wh[2][INC * HD];            // Wq, Wk f16 [k][n]
__device__ int8_t  g_wv8T[HD * INC];             // Wv^T [n][k] s8 x2873
__device__ __half  g_q[NN * HD];                 // qn f16
__device__ int8_t  g_k8T[HD * NN];               // kn^T [hm][n] s8 x127
__device__ int8_t  g_v8T[HD * NN];               // v^T  [hd][n] s8 x40
__device__ float g_colsum_p[512 * INC];
__device__ float g_colsum[INC];
__device__ float g_vsum[HD];
__device__ float g_ksum_p2[512 * HD];
__device__ float g_ksum[HD];
__device__ float g_kv_part[16 * 4 * DIM * DIM];  // dequantized fp32
__device__ __half g_kvb[4 * DIM * DIM];          // kv stacked [hm][d] f16
__device__ float g_invden[NN * 4];

// ---------------- helpers ----------------------------------------------------
__device__ __forceinline__ uint32_t smem_u32(const void* p) {
    return (uint32_t)__cvta_generic_to_shared(p);
}
__device__ __forceinline__ void ldsm4(uint32_t* r, uint32_t a) {
    asm volatile("ldmatrix.sync.aligned.m8n8.x4.shared.b16 {%0,%1,%2,%3}, [%4];"
        : "=r"(r[0]), "=r"(r[1]), "=r"(r[2]), "=r"(r[3]) : "r"(a));
}
__device__ __forceinline__ void ldsm4t(uint32_t* r, uint32_t a) {
    asm volatile("ldmatrix.sync.aligned.m8n8.x4.trans.shared.b16 {%0,%1,%2,%3}, [%4];"
        : "=r"(r[0]), "=r"(r[1]), "=r"(r[2]), "=r"(r[3]) : "r"(a));
}
// s8 mma, s32 accumulate, k=32
__device__ __forceinline__ void imma(int* d, const uint32_t* a, uint32_t b0, uint32_t b1) {
    asm volatile("mma.sync.aligned.m16n8k32.row.col.s32.s8.s8.s32 "
        "{%0,%1,%2,%3}, {%4,%5,%6,%7}, {%8,%9}, {%0,%1,%2,%3};"
        : "+r"(d[0]), "+r"(d[1]), "+r"(d[2]), "+r"(d[3])
        : "r"(a[0]), "r"(a[1]), "r"(a[2]), "r"(a[3]), "r"(b0), "r"(b1));
}
// f16 accumulate (q,k)
__device__ __forceinline__ void mma16816h(uint32_t* d, const uint32_t* a, const uint32_t* b) {
    asm volatile("mma.sync.aligned.m16n8k16.row.col.f16.f16.f16.f16 "
        "{%0,%1}, {%2,%3,%4,%5}, {%6,%7}, {%0,%1};"
        : "+r"(d[0]), "+r"(d[1])
        : "r"(a[0]), "r"(a[1]), "r"(a[2]), "r"(a[3]), "r"(b[0]), "r"(b[1]));
}
// f32 accumulate, f16 inputs (out)
__device__ __forceinline__ void mma16816f(float* d, const uint32_t* a, const uint32_t* b) {
    asm volatile("mma.sync.aligned.m16n8k16.row.col.f32.f16.f16.f32 "
        "{%0,%1,%2,%3}, {%4,%5,%6,%7}, {%8,%9}, {%0,%1,%2,%3};"
        : "+f"(d[0]), "+f"(d[1]), "+f"(d[2]), "+f"(d[3])
        : "r"(a[0]), "r"(a[1]), "r"(a[2]), "r"(a[3]), "r"(b[0]), "r"(b[1]));
}
__device__ __forceinline__ void cp16(void* s, const void* g) {
    asm volatile("cp.async.cg.shared.global [%0], [%1], 16;"
        :: "r"(smem_u32(s)), "l"(g));
}
__device__ __forceinline__ void cp_commit() { asm volatile("cp.async.commit_group;"); }
template<int W> __device__ __forceinline__ void cp_wait() {
    asm volatile("cp.async.wait_group %0;" :: "n"(W));
}
__device__ __forceinline__ int8_t to_s8(float f) {
    int v = __float2int_rn(f);
    return (int8_t)max(-127, min(127, v));
}

// ---------------- cvt_x: f16 + s8 + colsum partials --------------------------
__global__ void cvt_x_kernel(const float* __restrict__ x) {
    int p = blockIdx.x;                 // 256 blocks, 256 rows each
    int tid = threadIdx.x;              // 256
    int seg = tid & 127, half = tid >> 7;
    size_t r0 = (size_t)p * 256;
    float c0 = 0.f, c1 = 0.f, c2 = 0.f, c3 = 0.f;
    for (int i = half; i < 256; i += 2) {
        float4 f = ((const float4*)x)[(r0 + i) * 128 + seg];
        c0 += f.x; c1 += f.y; c2 += f.z; c3 += f.w;
        __half2* d = (__half2*)g_xh + (r0 + i) * 256 + seg * 2;
        d[0] = __floats2half2_rn(f.x, f.y);
        d[1] = __floats2half2_rn(f.z, f.w);
        uint32_t pk = (uint32_t)(uint8_t)to_s8(f.x * S_X)
                    | ((uint32_t)(uint8_t)to_s8(f.y * S_X) << 8)
                    | ((uint32_t)(uint8_t)to_s8(f.z * S_X) << 16)
                    | ((uint32_t)(uint8_t)to_s8(f.w * S_X) << 24);
        ((uint32_t*)g_x8)[(r0 + i) * 128 + seg] = pk;
    }
    float* dst = &g_colsum_p[(p * 2 + half) * INC + seg * 4];
    dst[0] = c0; dst[1] = c1; dst[2] = c2; dst[3] = c3;
}
__global__ void colsum_red_kernel() {
    int c = blockIdx.x * 256 + threadIdx.x;     // grid.x = 2
    float s = 0.f;
    for (int p = 0; p < 512; p++) s += g_colsum_p[p * INC + c];
    g_colsum[c] = s;
}
__global__ void vsum_kernel(const float* __restrict__ Wv, const float* __restrict__ bv) {
    int warp = threadIdx.x >> 5, lane = threadIdx.x & 31;
    int m = blockIdx.x * 8 + warp;               // grid = 128
    float s = 0.f;
    for (int kk = lane; kk < INC; kk += 32) s += g_colsum[kk] * Wv[kk * HD + m];
    #pragma unroll
    for (int o = 16; o > 0; o >>= 1) s += __shfl_xor_sync(0xffffffffu, s, o);
    if (lane == 0) g_vsum[m] = s + 65536.f * bv[m];
}

__global__ void cvt_wqk_kernel(const float* __restrict__ Wq, const float* __restrict__ Wk) {
    int which = blockIdx.y;
    const float* src = which == 0 ? Wq : Wk;
    int i = blockIdx.x * 256 + threadIdx.x;      // grid.x = 512
    float4 f = ((const float4*)src)[i];
    __half2* d2 = (__half2*)g_wh[which];
    d2[2 * i]     = __floats2half2_rn(f.x, f.y);
    d2[2 * i + 1] = __floats2half2_rn(f.z, f.w);
}
__global__ void cvt_wv8_kernel(const float* __restrict__ Wv) {
    int gid = blockIdx.x * 256 + threadIdx.x;    // 1024 blocks -> 262144
    int k2 = gid >> 10, n = gid & 1023;
    int8_t a = to_s8(Wv[(size_t)(2 * k2) * HD + n] * S_WV);
    int8_t b = to_s8(Wv[(size_t)(2 * k2 + 1) * HD + n] * S_WV);
    uint16_t pk = (uint16_t)(uint8_t)a | ((uint16_t)(uint8_t)b << 8);
    *(uint16_t*)&g_wv8T[(size_t)n * INC + 2 * k2] = pk;
}

// ============= s8 v projection: v = x @ Wv + bv, output v^T s8 ===============
#define A8PITCH 80
#define A8STG (128 * A8PITCH)
#define B8STG (256 * A8PITCH)
#define STG8 (A8STG + B8STG)
#define I8_SMEM (3 * STG8)

__global__ __launch_bounds__(256) void v8_kernel(const float* __restrict__ bv) {
    extern __shared__ char smc[];
    int n0 = blockIdx.x * 256;                   // grid (4, 512)
    size_t r0 = (size_t)blockIdx.y * 128;
    int tid = threadIdx.x, lane = tid & 31, warp = tid >> 5;
    int wm = (warp & 1) * 64, wn = (warp >> 1) * 64;
    int quad = lane >> 3, r8 = lane & 7;
    int crow = tid >> 2, cc = tid & 3;

    int acc[4][8][4];
    #pragma unroll
    for (int a = 0; a < 4; a++)
        #pragma unroll
        for (int b = 0; b < 8; b++)
            #pragma unroll
            for (int c = 0; c < 4; c++) acc[a][b][c] = 0;

    auto load_stage = [&](int st, int k0) {
        char* S = smc + st * STG8;
        #pragma unroll
        for (int j = 0; j < 2; j++) {
            int row = crow + j * 64;
            cp16(S + row * A8PITCH + cc * 16, &g_x8[(r0 + row) * INC + k0 + cc * 16]);
        }
        #pragma unroll
        for (int j = 0; j < 4; j++) {
            int row = crow + j * 64;
            cp16(S + A8STG + row * A8PITCH + cc * 16,
                 &g_wv8T[(size_t)(n0 + row) * INC + k0 + cc * 16]);
        }
        cp_commit();
    };

    load_stage(0, 0);
    load_stage(1, 64);
    #pragma unroll 1
    for (int it = 0; it < 8; it++) {
        int st = it % 3;
        if (it < 7) cp_wait<1>(); else cp_wait<0>();
        __syncthreads();
        if (it + 2 < 8) load_stage((it + 2) % 3, (it + 2) * 64);
        char* S = smc + st * STG8;
        #pragma unroll
        for (int kk = 0; kk < 2; kk++) {
            uint32_t af[4][4], bf[4][4];
            #pragma unroll
            for (int mi = 0; mi < 4; mi++)
                ldsm4(af[mi], smem_u32(S +
                    (wm + mi * 16 + (quad & 1) * 8 + r8) * A8PITCH + kk * 32 + (quad >> 1) * 16));
            #pragma unroll
            for (int nj = 0; nj < 4; nj++)
                ldsm4(bf[nj], smem_u32(S + A8STG +
                    (wn + nj * 16 + (quad & 1) * 8 + r8) * A8PITCH + kk * 32 + (quad >> 1) * 16));
            #pragma unroll
            for (int mi = 0; mi < 4; mi++)
                #pragma unroll
                for (int nj = 0; nj < 4; nj++) {
                    imma(acc[mi][2 * nj],     af[mi], bf[nj][0], bf[nj][2]);
                    imma(acc[mi][2 * nj + 1], af[mi], bf[nj][1], bf[nj][3]);
                }
        }
    }

    int group = lane >> 2, t4 = lane & 3;
    const float deq = 1.f / (S_X * S_WV);
    __syncthreads();                 // pipeline drained; reuse smem
    int8_t* tbuf = (int8_t*)smc;     // [256 cols][144 row-pitch]
    #pragma unroll
    for (int mi = 0; mi < 4; mi++)
        #pragma unroll
        for (int ni = 0; ni < 8; ni++) {
            int c = wn + ni * 8 + t4 * 2;
            int cg = n0 + c;
            float b0 = __ldg(&bv[cg]), b1 = __ldg(&bv[cg + 1]);
            int r = wm + mi * 16 + group;
            tbuf[c * 144 + r]           = to_s8(((float)acc[mi][ni][0] * deq + b0) * S_V);
            tbuf[(c + 1) * 144 + r]     = to_s8(((float)acc[mi][ni][1] * deq + b1) * S_V);
            tbuf[c * 144 + r + 8]       = to_s8(((float)acc[mi][ni][2] * deq + b0) * S_V);
            tbuf[(c + 1) * 144 + r + 8] = to_s8(((float)acc[mi][ni][3] * deq + b1) * S_V);
        }
    __syncthreads();
    {
        const uint4* src = (const uint4*)(tbuf + tid * 144);
        uint4* dst = (uint4*)&g_v8T[(size_t)(n0 + tid) * NN + r0];
        #pragma unroll
        for (int j = 0; j < 8; j++) dst[j] = src[j];
    }
}

// ====== f16 q,k GEMM + bias + L2-normalize; k: + ksum partials + kn^T s8 =====
#define APITCH 72
#define BPITCH 264
#define ASTG (128 * APITCH)
#define BSTG (64 * BPITCH)
#define QK_SMEM ((3 * (ASTG + BSTG)) * 2)

__global__ __launch_bounds__(256) void qk_kernel(const float* __restrict__ bq,
                                                 const float* __restrict__ bk) {
    extern __shared__ __half sm[];
    char* smc = (char*)sm;
    __half* As = sm;
    __half* Bs = sm + 3 * ASTG;

    int which = blockIdx.x >> 2;                 // grid (8, 512)
    int n0 = (blockIdx.x & 3) * 256;
    size_t r0 = (size_t)blockIdx.y * 128;
    const __half* __restrict__ B = g_wh[which];
    const float* __restrict__ bias = which == 0 ? bq : bk;

    int tid = threadIdx.x, lane = tid & 31, warp = tid >> 5;
    int wm = (warp & 1) * 64, wn = (warp >> 1) * 64;
    int quad = lane >> 3, r8 = lane & 7;
    int arow = tid >> 3, aseg = tid & 7;
    int brow = tid >> 5, bseg = tid & 31;

    uint32_t accA[4][8][2], accB[4][8][2];
    #pragma unroll
    for (int a = 0; a < 4; a++)
        #pragma unroll
        for (int b = 0; b < 8; b++) {
            accA[a][b][0] = 0u; accA[a][b][1] = 0u;
            accB[a][b][0] = 0u; accB[a][b][1] = 0u;
        }

    auto load_stage = [&](int st, int k0) {
        #pragma unroll
        for (int rr = 0; rr < 4; rr++)
            cp16(&As[st * ASTG + (arow + rr * 32) * APITCH + aseg * 8],
                 &g_xh[(r0 + arow + rr * 32) * INC + k0 + aseg * 8]);
        #pragma unroll
        for (int rr = 0; rr < 8; rr++)
            cp16(&Bs[st * BSTG + (brow + rr * 8) * BPITCH + bseg * 8],
                 &B[(size_t)(k0 + brow + rr * 8) * HD + n0 + bseg * 8]);
        cp_commit();
    };

    load_stage(0, 0);
    load_stage(1, 64);
    #pragma unroll 1
    for (int it = 0; it < 8; it++) {
        int st = it % 3;
        if (it < 7) cp_wait<1>(); else cp_wait<0>();
        __syncthreads();
        if (it + 2 < 8) load_stage((it + 2) % 3, (it + 2) * 64);
        uint32_t (*accC)[8][2] = (it < 4) ? accA : accB;
        #pragma unroll
        for (int ks = 0; ks < 64; ks += 16) {
            uint32_t af[4][4], bf[4][4];
            #pragma unroll
            for (int mi = 0; mi < 4; mi++)
                ldsm4(af[mi], smem_u32(&As[st * ASTG +
                    (wm + mi * 16 + (quad & 1) * 8 + r8) * APITCH + ks + (quad >> 1) * 8]));
            #pragma unroll
            for (int nj = 0; nj < 4; nj++)
                ldsm4t(bf[nj], smem_u32(&Bs[st * BSTG +
                    (ks + (quad & 1) * 8 + r8) * BPITCH + wn + nj * 16 + (quad >> 1) * 8]));
            #pragma unroll
            for (int mi = 0; mi < 4; mi++)
                #pragma unroll
                for (int nj = 0; nj < 4; nj++) {
                    mma16816h(accC[mi][2 * nj],     af[mi], &bf[nj][0]);
                    mma16816h(accC[mi][2 * nj + 1], af[mi], &bf[nj][2]);
                }
        }
    }

    float acc[4][8][4];
    #pragma unroll
    for (int mi = 0; mi < 4; mi++)
        #pragma unroll
        for (int ni = 0; ni < 8; ni++) {
            float2 a0 = __half22float2(*(__half2*)&accA[mi][ni][0]);
            float2 b0 = __half22float2(*(__half2*)&accB[mi][ni][0]);
            float2 a1 = __half22float2(*(__half2*)&accA[mi][ni][1]);
            float2 b1 = __half22float2(*(__half2*)&accB[mi][ni][1]);
            acc[mi][ni][0] = a0.x + b0.x; acc[mi][ni][1] = a0.y + b0.y;
            acc[mi][ni][2] = a1.x + b1.x; acc[mi][ni][3] = a1.y + b1.y;
        }

    int group = lane >> 2, t4 = lane & 3;
    float ss0[4] = {0.f, 0.f, 0.f, 0.f}, ss1[4] = {0.f, 0.f, 0.f, 0.f};
    #pragma unroll
    for (int mi = 0; mi < 4; mi++)
        #pragma unroll
        for (int ni = 0; ni < 8; ni++) {
            int c = n0 + wn + ni * 8 + t4 * 2;
            float b0 = __ldg(&bias[c]), b1 = __ldg(&bias[c + 1]);
            acc[mi][ni][0] += b0; acc[mi][ni][1] += b1;
            acc[mi][ni][2] += b0; acc[mi][ni][3] += b1;
            ss0[mi] += acc[mi][ni][0] * acc[mi][ni][0] + acc[mi][ni][1] * acc[mi][ni][1];
            ss1[mi] += acc[mi][ni][2] * acc[mi][ni][2] + acc[mi][ni][3] * acc[mi][ni][3];
        }

    #pragma unroll
    for (int mi = 0; mi < 4; mi++) {
        ss0[mi] += __shfl_xor_sync(0xffffffffu, ss0[mi], 1);
        ss0[mi] += __shfl_xor_sync(0xffffffffu, ss0[mi], 2);
        ss1[mi] += __shfl_xor_sync(0xffffffffu, ss1[mi], 1);
        ss1[mi] += __shfl_xor_sync(0xffffffffu, ss1[mi], 2);
    }
    float* ssbuf = (float*)smc;
    int wng = warp >> 1;
    if (t4 == 0) {
        #pragma unroll
        for (int mi = 0; mi < 4; mi++) {
            ssbuf[wng * 128 + wm + mi * 16 + group]     = ss0[mi];
            ssbuf[wng * 128 + wm + mi * 16 + group + 8] = ss1[mi];
        }
    }
    __syncthreads();
    #pragma unroll
    for (int mi = 0; mi < 4; mi++) {
        int ra = wm + mi * 16 + group;
        float s0 = ssbuf[ra] + ssbuf[128 + ra] + ssbuf[256 + ra] + ssbuf[384 + ra];
        int rb = ra + 8;
        float s1 = ssbuf[rb] + ssbuf[128 + rb] + ssbuf[256 + rb] + ssbuf[384 + rb];
        float i0 = rsqrtf(s0), i1 = rsqrtf(s1);
        #pragma unroll
        for (int ni = 0; ni < 8; ni++) {
            acc[mi][ni][0] *= i0; acc[mi][ni][1] *= i0;
            acc[mi][ni][2] *= i1; acc[mi][ni][3] *= i1;
        }
    }

    if (which == 0) {    // q: store f16
        #pragma unroll
        for (int mi = 0; mi < 4; mi++) {
            size_t rA = r0 + wm + mi * 16 + group;
            #pragma unroll
            for (int ni = 0; ni < 8; ni++) {
                int c = n0 + wn + ni * 8 + t4 * 2;
                *(__half2*)&g_q[rA * HD + c] =
                    __floats2half2_rn(acc[mi][ni][0], acc[mi][ni][1]);
                *(__half2*)&g_q[(rA + 8) * HD + c] =
                    __floats2half2_rn(acc[mi][ni][2], acc[mi][ni][3]);
            }
        }
    } else {             // k: ksum partials + kn^T s8 (x127)
        float cs[8][2];
        #pragma unroll
        for (int ni = 0; ni < 8; ni++) {
            cs[ni][0] = 0.f; cs[ni][1] = 0.f;
            #pragma unroll
            for (int mi = 0; mi < 4; mi++) {
                cs[ni][0] += acc[mi][ni][0] + acc[mi][ni][2];
                cs[ni][1] += acc[mi][ni][1] + acc[mi][ni][3];
            }
            #pragma unroll
            for (int o = 4; o < 32; o <<= 1) {
                cs[ni][0] += __shfl_xor_sync(0xffffffffu, cs[ni][0], o);
                cs[ni][1] += __shfl_xor_sync(0xffffffffu, cs[ni][1], o);
            }
        }
        __syncthreads();
        float* cbuf = (float*)smc;
        if (lane < 4) {
            #pragma unroll
            for (int ni = 0; ni < 8; ni++) {
                cbuf[warp * 64 + ni * 8 + lane * 2]     = cs[ni][0];
                cbuf[warp * 64 + ni * 8 + lane * 2 + 1] = cs[ni][1];
            }
        }
        __syncthreads();
        {
            int g2 = tid >> 6, ccx = tid & 63;
            float s = cbuf[(2 * g2) * 64 + ccx] + cbuf[(2 * g2 + 1) * 64 + ccx];
            g_ksum_p2[blockIdx.y * HD + n0 + g2 * 64 + ccx] = s;
        }
        __syncthreads();
        int8_t* tbuf = (int8_t*)smc;
        #pragma unroll
        for (int mi = 0; mi < 4; mi++)
            #pragma unroll
            for (int ni = 0; ni < 8; ni++) {
                int c = wn + ni * 8 + t4 * 2;
                int r = wm + mi * 16 + group;
                tbuf[c * 144 + r]           = to_s8(acc[mi][ni][0] * S_K);
                tbuf[(c + 1) * 144 + r]     = to_s8(acc[mi][ni][1] * S_K);
                tbuf[c * 144 + r + 8]       = to_s8(acc[mi][ni][2] * S_K);
                tbuf[(c + 1) * 144 + r + 8] = to_s8(acc[mi][ni][3] * S_K);
            }
        __syncthreads();
        const uint4* src = (const uint4*)(tbuf + tid * 144);
        uint4* dst = (uint4*)&g_k8T[(size_t)(n0 + tid) * NN + r0];
        #pragma unroll
        for (int j = 0; j < 8; j++) dst[j] = src[j];
    }
}

// ---------------- ksum final reduce ------------------------------------------
__global__ void ksum_red_kernel() {
    int c = blockIdx.x * 256 + threadIdx.x;   // grid.x = 4
    float s = 0.f;
    for (int p = 0; p < 512; p++) s += g_ksum_p2[p * HD + c];
    g_ksum[c] = s;
}

// ---------------- invden[n,h] = 1/(qn . ksum[h] + N) -------------------------
__global__ void invden_kernel() {
    int wg = blockIdx.x * 8 + (threadIdx.x >> 5);   // wg = n*4+h
    int lane = threadIdx.x & 31, h = wg & 3;
    size_t base = (size_t)wg * 256 + lane * 8;
    uint4 raw = *(const uint4*)&g_q[base];
    __half2* p = (__half2*)&raw;
    const float* ks = &g_ksum[h * 256 + lane * 8];
    float s = 0.f;
    #pragma unroll
    for (int i = 0; i < 4; i++) {
        float2 f = __half22float2(p[i]);
        s += f.x * ks[2 * i] + f.y * ks[2 * i + 1];
    }
    #pragma unroll
    for (int o = 16; o > 0; o >>= 1) s += __shfl_xor_sync(0xffffffffu, s, o);
    if (lane == 0) g_invden[wg] = 1.f / (s + 65536.f);
}

// ========= s8 kv GEMM: kv[h][m][d] = sum_n kn^T x v^T, split-K ===============
__global__ __launch_bounds__(256) void kv8_kernel() {
    extern __shared__ char smc[];
    int m0 = blockIdx.x * 128;                   // grid (2, 1, 64)
    int h = blockIdx.z & 3;
    int chunk = blockIdx.z >> 2;
    size_t nb = (size_t)chunk * 4096;
    int tid = threadIdx.x, lane = tid & 31, warp = tid >> 5;
    int wm = (warp & 1) * 64, wn = (warp >> 1) * 64;
    int quad = lane >> 3, r8 = lane & 7;
    int crow = tid >> 2, cc = tid & 3;

    int acc[4][8][4];
    #pragma unroll
    for (int a = 0; a < 4; a++)
        #pragma unroll
        for (int b = 0; b < 8; b++)
            #pragma unroll
            for (int c = 0; c < 4; c++) acc[a][b][c] = 0;

    auto load_stage = [&](int st, int k0) {
        char* S = smc + st * STG8;
        #pragma unroll
        for (int j = 0; j < 2; j++) {     // A: kn^T rows m
            int row = crow + j * 64;
            cp16(S + row * A8PITCH + cc * 16,
                 &g_k8T[(size_t)(h * 256 + m0 + row) * NN + nb + k0 + cc * 16]);
        }
        #pragma unroll
        for (int j = 0; j < 4; j++) {     // B: v^T rows d
            int row = crow + j * 64;
            cp16(S + A8STG + row * A8PITCH + cc * 16,
                 &g_v8T[(size_t)(h * 256 + row) * NN + nb + k0 + cc * 16]);
        }
        cp_commit();
    };

    load_stage(0, 0);
    load_stage(1, 64);
    #pragma unroll 1
    for (int it = 0; it < 64; it++) {
        int st = it % 3;
        if (it < 63) cp_wait<1>(); else cp_wait<0>();
        __syncthreads();
        if (it + 2 < 64) load_stage((it + 2) % 3, (it + 2) * 64);
        char* S = smc + st * STG8;
        #pragma unroll
        for (int kk = 0; kk < 2; kk++) {
            uint32_t af[4][4], bf[4][4];
            #pragma unroll
            for (int mi = 0; mi < 4; mi++)
                ldsm4(af[mi], smem_u32(S +
                    (wm + mi * 16 + (quad & 1) * 8 + r8) * A8PITCH + kk * 32 + (quad >> 1) * 16));
            #pragma unroll
            for (int nj = 0; nj < 4; nj++)
                ldsm4(bf[nj], smem_u32(S + A8STG +
                    (wn + nj * 16 + (quad & 1) * 8 + r8) * A8PITCH + kk * 32 + (quad >> 1) * 16));
            #pragma unroll
            for (int mi = 0; mi < 4; mi++)
                #pragma unroll
                for (int nj = 0; nj < 4; nj++) {
                    imma(acc[mi][2 * nj],     af[mi], bf[nj][0], bf[nj][2]);
                    imma(acc[mi][2 * nj + 1], af[mi], bf[nj][1], bf[nj][3]);
                }
        }
    }
    int group = lane >> 2, t4 = lane & 3;
    const float deq = 1.f / (S_K * S_V);
    float* dst = &g_kv_part[(size_t)chunk * (4 * DIM * DIM) + h * (DIM * DIM)];
    #pragma unroll
    for (int mi = 0; mi < 4; mi++) {
        int rm = m0 + wm + mi * 16 + group;
        #pragma unroll
        for (int ni = 0; ni < 8; ni++) {
            int c = wn + ni * 8 + t4 * 2;
            *(float2*)&dst[rm * 256 + c] =
                make_float2((float)acc[mi][ni][0] * deq, (float)acc[mi][ni][1] * deq);
            *(float2*)&dst[(rm + 8) * 256 + c] =
                make_float2((float)acc[mi][ni][2] * deq, (float)acc[mi][ni][3] * deq);
        }
    }
}

__global__ void kvred_kernel() {
    int i = blockIdx.x * 256 + threadIdx.x;      // 1024 blocks
    float s = 0.f;
    #pragma unroll
    for (int p = 0; p < 16; p++) s += g_kv_part[p * (4 * DIM * DIM) + i];
    g_kvb[i] = __float2half(s);
}

// ------ out = 0.25*((q*invden*65536) @ kv / 65536 + rowoff), K=1024, f16 -----
#define OAPITCH 72
#define OASTG (128 * OAPITCH)
#define OBSTG (64 * BPITCH)
#define OUT_SMEM_BYTES ((3 * (OASTG + OBSTG)) * 2)

__global__ __launch_bounds__(512) void out_kernel(float* __restrict__ out) {
    extern __shared__ __half sm[];
    __half* As = sm;
    __half* Bs = sm + 3 * OASTG;

    size_t r0 = (size_t)blockIdx.y * 128;
    int tid = threadIdx.x, lane = tid & 31, warp = tid >> 5;
    int wm = (warp & 3) * 32, wn = (warp >> 2) * 64;
    int quad = lane >> 3, r8 = lane & 7;
    int arow = tid >> 3, aseg = tid & 7;
    int brow = tid >> 5, bseg = tid & 31;

    float acc[2][8][4];
    #pragma unroll
    for (int a = 0; a < 2; a++)
        #pragma unroll
        for (int b = 0; b < 8; b++)
            #pragma unroll
            for (int c = 0; c < 4; c++) acc[a][b][c] = 0.f;

    uint4 aR[2];
    float invR[2];

    auto ldgA = [&](int kit) {
        int k0 = kit * 64, h = k0 >> 8;
        #pragma unroll
        for (int rr = 0; rr < 2; rr++) {
            size_t row = r0 + arow + rr * 64;
            aR[rr] = *(const uint4*)&g_q[row * HD + k0 + aseg * 8];
            invR[rr] = g_invden[row * 4 + h];
        }
    };
    auto stsA = [&](int kit) {       // scale by invden*65536 (avoid f16 underflow)
        int st = kit % 3;
        #pragma unroll
        for (int rr = 0; rr < 2; rr++) {
            __half2* p = (__half2*)&aR[rr];
            float iv = invR[rr] * 65536.f;
            uint4 o;
            __half2* q = (__half2*)&o;
            #pragma unroll
            for (int j = 0; j < 4; j++) {
                float2 f = __half22float2(p[j]);
                q[j] = __floats2half2_rn(f.x * iv, f.y * iv);
            }
            *(uint4*)&As[st * OASTG + (arow + rr * 64) * OAPITCH + aseg * 8] = o;
        }
    };
    auto cpB = [&](int kit) {
        int st = kit % 3, k0 = kit * 64;
        #pragma unroll
        for (int rr = 0; rr < 4; rr++)
            cp16(&Bs[st * OBSTG + (brow + rr * 16) * BPITCH + bseg * 8],
                 &g_kvb[(size_t)(k0 + brow + rr * 16) * 256 + bseg * 8]);
        cp_commit();
    };

    ldgA(0); stsA(0);
    ldgA(1);
    cpB(0); cpB(1);
    #pragma unroll 1
    for (int it = 0; it < 16; it++) {
        int st = it % 3;
        if (it < 15) cp_wait<1>(); else cp_wait<0>();
        __syncthreads();
        if (it + 1 < 16) stsA(it + 1);
        if (it + 2 < 16) { ldgA(it + 2); cpB(it + 2); }
        #pragma unroll
        for (int ks = 0; ks < 64; ks += 16) {
            uint32_t af[2][4], bf[4][4];
            #pragma unroll
            for (int mi = 0; mi < 2; mi++)
                ldsm4(af[mi], smem_u32(&As[st * OASTG +
                    (wm + mi * 16 + (quad & 1) * 8 + r8) * OAPITCH + ks + (quad >> 1) * 8]));
            #pragma unroll
            for (int nj = 0; nj < 4; nj++)
                ldsm4t(bf[nj], smem_u32(&Bs[st * OBSTG +
                    (ks + (quad & 1) * 8 + r8) * BPITCH + wn + nj * 16 + (quad >> 1) * 8]));
            #pragma unroll
            for (int mi = 0; mi < 2; mi++)
                #pragma unroll
                for (int nj = 0; nj < 4; nj++) {
                    mma16816f(acc[mi][2 * nj],     af[mi], &bf[nj][0]);
                    mma16816f(acc[mi][2 * nj + 1], af[mi], &bf[nj][2]);
                }
        }
    }

    const float inv64k = 1.f / 65536.f;
    int group = lane >> 2, t4 = lane & 3;
    #pragma unroll
    for (int mi = 0; mi < 2; mi++) {
        size_t rA = r0 + wm + mi * 16 + group;
        size_t rB = rA + 8;
        float ia[4], ib[4];
        #pragma unroll
        for (int h = 0; h < 4; h++) {
            ia[h] = g_invden[rA * 4 + h];
            ib[h] = g_invden[rB * 4 + h];
        }
        #pragma unroll
        for (int ni = 0; ni < 8; ni++) {
            int c = wn + ni * 8 + t4 * 2;
            float roa0 = 0.f, roa1 = 0.f, rob0 = 0.f, rob1 = 0.f;
            #pragma unroll
            for (int h = 0; h < 4; h++) {
                float v0 = __ldg(&g_vsum[h * 256 + c]);
                float v1 = __ldg(&g_vsum[h * 256 + c + 1]);
                roa0 += ia[h] * v0; roa1 += ia[h] * v1;
                rob0 += ib[h] * v0; rob1 += ib[h] * v1;
            }
            *(float2*)&out[rA * 256 + c] =
                make_float2(0.25f * (acc[mi][ni][0] * inv64k + roa0),
                            0.25f * (acc[mi][ni][1] * inv64k + roa1));
            *(float2*)&out[rB * 256 + c] =
                make_float2(0.25f * (acc[mi][ni][2] * inv64k + rob0),
                            0.25f * (acc[mi][ni][3] * inv64k + rob1));
        }
    }
}

// ---------------- launch -----------------------------------------------------
extern "C" void kernel_launch(void* const* d_in, const int* in_sizes, int n_in,
                              void* d_out, int out_size) {
    const float* x  = (const float*)d_in[0];
    const float* Wq = (const float*)d_in[1];
    const float* bq = (const float*)d_in[2];
    const float* Wk = (const float*)d_in[3];
    const float* bk = (const float*)d_in[4];
    const float* Wv = (const float*)d_in[5];
    const float* bv = (const float*)d_in[6];
    float* out = (float*)d_out;

    cudaFuncSetAttribute(qk_kernel,  cudaFuncAttributeMaxDynamicSharedMemorySize, QK_SMEM);
    cudaFuncSetAttribute(v8_kernel,  cudaFuncAttributeMaxDynamicSharedMemorySize, I8_SMEM);
    cudaFuncSetAttribute(kv8_kernel, cudaFuncAttributeMaxDynamicSharedMemorySize, I8_SMEM);
    cudaFuncSetAttribute(out_kernel, cudaFuncAttributeMaxDynamicSharedMemorySize, OUT_SMEM_BYTES);

    cvt_x_kernel<<<256, 256>>>(x);                       // 0
    cvt_wqk_kernel<<<dim3(512, 2), 256>>>(Wq, Wk);       // 1
    cvt_wv8_kernel<<<1024, 256>>>(Wv);                   // 2
    v8_kernel<<<dim3(4, 512), 256, I8_SMEM>>>(bv);       // 3 (profiled: s8 rate test)
    qk_kernel<<<dim3(8, 512), 256, QK_SMEM>>>(bq, bk);   // 4
    colsum_red_kernel<<<2, 256>>>();                     // 5
    vsum_kernel<<<128, 256>>>(Wv, bv);                   // 6
    ksum_red_kernel<<<4, 256>>>();                       // 7
    invden_kernel<<<32768, 256>>>();                     // 8
    kv8_kernel<<<dim3(2, 1, 64), 256, I8_SMEM>>>();      // 9
    kvred_kernel<<<1024, 256>>>();                       // 10
    out_kernel<<<dim3(1, 512), 512, OUT_SMEM_BYTES>>>(out); // 11
}

// round 10
// speedup vs baseline: 1.4983x; 1.4983x over previous
#include <cuda_runtime.h>
#include <cuda_fp16.h>
#include <cstdint>

#define NN   65536
#define INC  512
#define HD   1024
#define DIM  256

// ---------------- scratch (device globals) -----------------------------------
__device__ __half g_xh[NN * INC];
__device__ __half g_wh[3][INC * HD];
__device__ __half g_q[NN * HD];
__device__ __half g_k[NN * HD];
__device__ __half g_v[NN * HD];
__device__ float g_colsum_p[512 * INC];
__device__ float g_colsum[INC];
__device__ float g_vsum[HD];
__device__ float g_ksum_p2[512 * HD];            // per-rowblock col partials of kn
__device__ float g_ksum[HD];
__device__ float g_kv_part[16 * 4 * DIM * DIM];
__device__ __half g_kvb[4 * DIM * DIM];          // stacked [h*256+m][256]
__device__ float g_invden[NN * 4];

// ---------------- helpers ----------------------------------------------------
__device__ __forceinline__ uint32_t smem_u32(const void* p) {
    return (uint32_t)__cvta_generic_to_shared(p);
}
__device__ __forceinline__ void ldsm4(uint32_t* r, uint32_t a) {
    asm volatile("ldmatrix.sync.aligned.m8n8.x4.shared.b16 {%0,%1,%2,%3}, [%4];"
        : "=r"(r[0]), "=r"(r[1]), "=r"(r[2]), "=r"(r[3]) : "r"(a));
}
__device__ __forceinline__ void ldsm4t(uint32_t* r, uint32_t a) {
    asm volatile("ldmatrix.sync.aligned.m8n8.x4.trans.shared.b16 {%0,%1,%2,%3}, [%4];"
        : "=r"(r[0]), "=r"(r[1]), "=r"(r[2]), "=r"(r[3]) : "r"(a));
}
// f16 accumulate (kv kernel)
__device__ __forceinline__ void mma16816h(uint32_t* d, const uint32_t* a, const uint32_t* b) {
    asm volatile("mma.sync.aligned.m16n8k16.row.col.f16.f16.f16.f16 "
        "{%0,%1}, {%2,%3,%4,%5}, {%6,%7}, {%0,%1};"
        : "+r"(d[0]), "+r"(d[1])
        : "r"(a[0]), "r"(a[1]), "r"(a[2]), "r"(a[3]), "r"(b[0]), "r"(b[1]));
}
// f32 accumulate, f16 inputs (qkv + out)
__device__ __forceinline__ void mma16816f(float* d, const uint32_t* a, const uint32_t* b) {
    asm volatile("mma.sync.aligned.m16n8k16.row.col.f32.f16.f16.f32 "
        "{%0,%1,%2,%3}, {%4,%5,%6,%7}, {%8,%9}, {%0,%1,%2,%3};"
        : "+f"(d[0]), "+f"(d[1]), "+f"(d[2]), "+f"(d[3])
        : "r"(a[0]), "r"(a[1]), "r"(a[2]), "r"(a[3]), "r"(b[0]), "r"(b[1]));
}
__device__ __forceinline__ void cp16(void* s, const void* g) {
    asm volatile("cp.async.cg.shared.global [%0], [%1], 16;"
        :: "r"(smem_u32(s)), "l"(g));
}
__device__ __forceinline__ void cp_commit() { asm volatile("cp.async.commit_group;"); }
template<int W> __device__ __forceinline__ void cp_wait() {
    asm volatile("cp.async.wait_group %0;" :: "n"(W));
}

// ---------------- cvt_x + colsum partials (fused) ----------------------------
__global__ void cvt_x_kernel(const float* __restrict__ x) {
    int p = blockIdx.x;                 // 256 blocks, 256 rows each
    int tid = threadIdx.x;              // 256
    int seg = tid & 127, half = tid >> 7;
    size_t r0 = (size_t)p * 256;
    float c0 = 0.f, c1 = 0.f, c2 = 0.f, c3 = 0.f;
    for (int i = half; i < 256; i += 2) {
        float4 f = ((const float4*)x)[(r0 + i) * 128 + seg];
        c0 += f.x; c1 += f.y; c2 += f.z; c3 += f.w;
        __half2* d = (__half2*)g_xh + (r0 + i) * 256 + seg * 2;
        d[0] = __floats2half2_rn(f.x, f.y);
        d[1] = __floats2half2_rn(f.z, f.w);
    }
    float* dst = &g_colsum_p[(p * 2 + half) * INC + seg * 4];
    dst[0] = c0; dst[1] = c1; dst[2] = c2; dst[3] = c3;
}
__global__ void colsum_red_kernel() {
    int c = blockIdx.x * 256 + threadIdx.x;     // grid.x = 2
    float s = 0.f;
    for (int p = 0; p < 512; p++) s += g_colsum_p[p * INC + c];
    g_colsum[c] = s;
}
__global__ void vsum_kernel(const float* __restrict__ Wv, const float* __restrict__ bv) {
    int warp = threadIdx.x >> 5, lane = threadIdx.x & 31;
    int m = blockIdx.x * 8 + warp;               // grid = 128
    float s = 0.f;
    for (int kk = lane; kk < INC; kk += 32) s += g_colsum[kk] * Wv[kk * HD + m];
    #pragma unroll
    for (int o = 16; o > 0; o >>= 1) s += __shfl_xor_sync(0xffffffffu, s, o);
    if (lane == 0) g_vsum[m] = s + 65536.f * bv[m];
}

__global__ void cvt_w_kernel(const float* __restrict__ Wq,
                             const float* __restrict__ Wk,
                             const float* __restrict__ Wv) {
    int which = blockIdx.y;
    const float* src = which == 0 ? Wq : which == 1 ? Wk : Wv;
    int i = blockIdx.x * 256 + threadIdx.x;      // grid.x = 512
    float4 f = ((const float4*)src)[i];
    __half2* d2 = (__half2*)g_wh[which];
    d2[2 * i]     = __floats2half2_rn(f.x, f.y);
    d2[2 * i + 1] = __floats2half2_rn(f.z, f.w);
}

// ---------------- fused QKV GEMM + bias + (q,k) L2-normalize + ksum ----------
// CTA tile 128x256, 256 threads (8 warps), warp tile 64x64, k=64, 3-stage
// cp.async; f32 accumulators (f16 inputs).
#define APITCH 72
#define BPITCH 264
#define ASTG (128 * APITCH)
#define BSTG (64 * BPITCH)
#define GEMM_SMEM_BYTES ((3 * (ASTG + BSTG)) * 2)

__global__ __launch_bounds__(256) void qkv_kernel(const float* __restrict__ bq,
                                                  const float* __restrict__ bk,
                                                  const float* __restrict__ bv) {
    extern __shared__ __half sm[];
    char* smc = (char*)sm;
    __half* As = sm;                  // [3][128][APITCH]
    __half* Bs = sm + 3 * ASTG;       // [3][64][BPITCH]

    int which = blockIdx.x >> 2;
    int n0 = (blockIdx.x & 3) * 256;
    size_t r0 = (size_t)blockIdx.y * 128;
    const __half* __restrict__ B = g_wh[which];
    __half* __restrict__ C = which == 0 ? g_q : which == 1 ? g_k : g_v;
    const float* __restrict__ bias = which == 0 ? bq : which == 1 ? bk : bv;

    int tid = threadIdx.x, lane = tid & 31, warp = tid >> 5;
    int wm = (warp & 1) * 64, wn = (warp >> 1) * 64;   // 2 m-groups x 4 n-groups
    int quad = lane >> 3, r8 = lane & 7;
    int arow = tid >> 3, aseg = tid & 7;
    int brow = tid >> 5, bseg = tid & 31;

    float acc[4][8][4];
    #pragma unroll
    for (int a = 0; a < 4; a++)
        #pragma unroll
        for (int b = 0; b < 8; b++)
            #pragma unroll
            for (int c = 0; c < 4; c++) acc[a][b][c] = 0.f;

    auto load_stage = [&](int st, int k0) {
        #pragma unroll
        for (int rr = 0; rr < 4; rr++)
            cp16(&As[st * ASTG + (arow + rr * 32) * APITCH + aseg * 8],
                 &g_xh[(r0 + arow + rr * 32) * INC + k0 + aseg * 8]);
        #pragma unroll
        for (int rr = 0; rr < 8; rr++)
            cp16(&Bs[st * BSTG + (brow + rr * 8) * BPITCH + bseg * 8],
                 &B[(size_t)(k0 + brow + rr * 8) * HD + n0 + bseg * 8]);
        cp_commit();
    };

    load_stage(0, 0);
    load_stage(1, 64);
    #pragma unroll 1
    for (int it = 0; it < 8; it++) {
        int st = it % 3;
        if (it < 7) cp_wait<1>(); else cp_wait<0>();
        __syncthreads();
        if (it + 2 < 8) load_stage((it + 2) % 3, (it + 2) * 64);
        #pragma unroll
        for (int ks = 0; ks < 64; ks += 16) {
            uint32_t af[4][4], bf[4][4];
            #pragma unroll
            for (int mi = 0; mi < 4; mi++)
                ldsm4(af[mi], smem_u32(&As[st * ASTG +
                    (wm + mi * 16 + (quad & 1) * 8 + r8) * APITCH + ks + (quad >> 1) * 8]));
            #pragma unroll
            for (int nj = 0; nj < 4; nj++)
                ldsm4t(bf[nj], smem_u32(&Bs[st * BSTG +
                    (ks + (quad & 1) * 8 + r8) * BPITCH + wn + nj * 16 + (quad >> 1) * 8]));
            #pragma unroll
            for (int mi = 0; mi < 4; mi++)
                #pragma unroll
                for (int nj = 0; nj < 4; nj++) {
                    mma16816f(acc[mi][2 * nj],     af[mi], &bf[nj][0]);
                    mma16816f(acc[mi][2 * nj + 1], af[mi], &bf[nj][2]);
                }
        }
    }

    int group = lane >> 2, t4 = lane & 3;
    // bias + per-row sum of squares
    float ss0[4] = {0.f, 0.f, 0.f, 0.f}, ss1[4] = {0.f, 0.f, 0.f, 0.f};
    #pragma unroll
    for (int mi = 0; mi < 4; mi++)
        #pragma unroll
        for (int ni = 0; ni < 8; ni++) {
            int c = n0 + wn + ni * 8 + t4 * 2;
            float b0 = __ldg(&bias[c]), b1 = __ldg(&bias[c + 1]);
            acc[mi][ni][0] += b0; acc[mi][ni][1] += b1;
            acc[mi][ni][2] += b0; acc[mi][ni][3] += b1;
            ss0[mi] += acc[mi][ni][0] * acc[mi][ni][0] + acc[mi][ni][1] * acc[mi][ni][1];
            ss1[mi] += acc[mi][ni][2] * acc[mi][ni][2] + acc[mi][ni][3] * acc[mi][ni][3];
        }

    if (which < 2) {   // normalize q,k rows (tile n-range == one full head)
        #pragma unroll
        for (int mi = 0; mi < 4; mi++) {
            ss0[mi] += __shfl_xor_sync(0xffffffffu, ss0[mi], 1);
            ss0[mi] += __shfl_xor_sync(0xffffffffu, ss0[mi], 2);
            ss1[mi] += __shfl_xor_sync(0xffffffffu, ss1[mi], 1);
            ss1[mi] += __shfl_xor_sync(0xffffffffu, ss1[mi], 2);
        }
        float* ssbuf = (float*)smc;   // pipeline finished; smem reusable
        int wng = warp >> 1;          // n-group 0..3
        if (t4 == 0) {
            #pragma unroll
            for (int mi = 0; mi < 4; mi++) {
                ssbuf[wng * 128 + wm + mi * 16 + group]     = ss0[mi];
                ssbuf[wng * 128 + wm + mi * 16 + group + 8] = ss1[mi];
            }
        }
        __syncthreads();
        #pragma unroll
        for (int mi = 0; mi < 4; mi++) {
            int ra = wm + mi * 16 + group;
            float s0 = ssbuf[ra] + ssbuf[128 + ra] + ssbuf[256 + ra] + ssbuf[384 + ra];
            int rb = ra + 8;
            float s1 = ssbuf[rb] + ssbuf[128 + rb] + ssbuf[256 + rb] + ssbuf[384 + rb];
            float i0 = rsqrtf(s0), i1 = rsqrtf(s1);
            #pragma unroll
            for (int ni = 0; ni < 8; ni++) {
                acc[mi][ni][0] *= i0; acc[mi][ni][1] *= i0;
                acc[mi][ni][2] *= i1; acc[mi][ni][3] *= i1;
            }
        }
    }

    #pragma unroll
    for (int mi = 0; mi < 4; mi++) {
        size_t rA = r0 + wm + mi * 16 + group;
        #pragma unroll
        for (int ni = 0; ni < 8; ni++) {
            int c = n0 + wn + ni * 8 + t4 * 2;
            *(__half2*)&C[rA * HD + c] =
                __floats2half2_rn(acc[mi][ni][0], acc[mi][ni][1]);
            *(__half2*)&C[(rA + 8) * HD + c] =
                __floats2half2_rn(acc[mi][ni][2], acc[mi][ni][3]);
        }
    }

    // fused ksum partials: column sums of this 128x256 kn tile
    if (which == 1) {
        float cs[8][2];
        #pragma unroll
        for (int ni = 0; ni < 8; ni++) {
            cs[ni][0] = 0.f; cs[ni][1] = 0.f;
            #pragma unroll
            for (int mi = 0; mi < 4; mi++) {
                cs[ni][0] += acc[mi][ni][0] + acc[mi][ni][2];
                cs[ni][1] += acc[mi][ni][1] + acc[mi][ni][3];
            }
            #pragma unroll
            for (int o = 4; o < 32; o <<= 1) {
                cs[ni][0] += __shfl_xor_sync(0xffffffffu, cs[ni][0], o);
                cs[ni][1] += __shfl_xor_sync(0xffffffffu, cs[ni][1], o);
            }
        }
        __syncthreads();
        float* cbuf = (float*)smc;    // [8 warps][64 cols]
        if (lane < 4) {
            #pragma unroll
            for (int ni = 0; ni < 8; ni++) {
                cbuf[warp * 64 + ni * 8 + lane * 2]     = cs[ni][0];
                cbuf[warp * 64 + ni * 8 + lane * 2 + 1] = cs[ni][1];
            }
        }
        __syncthreads();
        int g2 = tid >> 6, cc = tid & 63;
        float s = cbuf[(2 * g2) * 64 + cc] + cbuf[(2 * g2 + 1) * 64 + cc];
        g_ksum_p2[blockIdx.y * HD + n0 + g2 * 64 + cc] = s;
    }
}

// ---------------- ksum final reduce ------------------------------------------
__global__ void ksum_red_kernel() {
    int c = blockIdx.x * 256 + threadIdx.x;   // grid.x = 4
    float s = 0.f;
    for (int p = 0; p < 512; p++) s += g_ksum_p2[p * HD + c];
    g_ksum[c] = s;
}

// ---------------- invden[n,h] = 1/(qn . ksum[h] + N) -------------------------
__global__ void invden_kernel() {
    int wg = blockIdx.x * 8 + (threadIdx.x >> 5);   // wg = n*4+h
    int lane = threadIdx.x & 31, h = wg & 3;
    size_t base = (size_t)wg * 256 + lane * 8;
    uint4 raw = *(const uint4*)&g_q[base];
    __half2* p = (__half2*)&raw;
    const float* ks = &g_ksum[h * 256 + lane * 8];
    float s = 0.f;
    #pragma unroll
    for (int i = 0; i < 4; i++) {
        float2 f = __half22float2(p[i]);
        s += f.x * ks[2 * i] + f.y * ks[2 * i + 1];
    }
    #pragma unroll
    for (int o = 16; o > 0; o >>= 1) s += __shfl_xor_sync(0xffffffffu, s, o);
    if (lane == 0) g_invden[wg] = 1.f / (s + 65536.f);
}

// ---------------- kv[h] = kn^T @ v, split-K, f16-acc dual chain --------------
#define KVA_PITCH 136
#define KVB_PITCH 264
#define KVA_STG (64 * KVA_PITCH)
#define KVB_STG (64 * KVB_PITCH)
#define KV_SMEM_BYTES ((3 * (KVA_STG + KVB_STG)) * 2)

__global__ __launch_bounds__(512) void kv_kernel() {
    extern __shared__ __half sm[];
    __half* As = sm;                   // [3][64][KVA_PITCH]  kn[n][m]
    __half* Bs = sm + 3 * KVA_STG;     // [3][64][KVB_PITCH]  v[n][d]

    int tid = threadIdx.x, lane = tid & 31, warp = tid >> 5;
    int wm = (warp & 3) * 32, wn = (warp >> 2) * 64;
    int h = blockIdx.z & 3;
    int chunk = blockIdx.z >> 2;
    size_t n0 = (size_t)chunk * 4096;
    int m0 = blockIdx.y * 128;
    int quad = lane >> 3, r8 = lane & 7;
    int arow = tid >> 4, aseg = tid & 15;
    int brow = tid >> 5, bseg = tid & 31;

    uint32_t accA[2][8][2], accB[2][8][2];
    #pragma unroll
    for (int a = 0; a < 2; a++)
        #pragma unroll
        for (int b = 0; b < 8; b++) {
            accA[a][b][0] = 0u; accA[a][b][1] = 0u;
            accB[a][b][0] = 0u; accB[a][b][1] = 0u;
        }

    auto load_stage = [&](int st, int kk) {
        #pragma unroll
        for (int rr = 0; rr < 2; rr++)
            cp16(&As[st * KVA_STG + (arow + rr * 32) * KVA_PITCH + aseg * 8],
                 &g_k[(n0 + kk + arow + rr * 32) * HD + h * 256 + m0 + aseg * 8]);
        #pragma unroll
        for (int rr = 0; rr < 4; rr++)
            cp16(&Bs[st * KVB_STG + (brow + rr * 16) * KVB_PITCH + bseg * 8],
                 &g_v[(n0 + kk + brow + rr * 16) * HD + h * 256 + bseg * 8]);
        cp_commit();
    };

    load_stage(0, 0);
    load_stage(1, 64);
    #pragma unroll 1
    for (int it = 0; it < 64; it++) {
        int st = it % 3;
        if (it < 63) cp_wait<1>(); else cp_wait<0>();
        __syncthreads();
        if (it + 2 < 64) load_stage((it + 2) % 3, (it + 2) * 64);
        uint32_t (*accC)[8][2] = (it < 32) ? accA : accB;
        #pragma unroll
        for (int ks = 0; ks < 64; ks += 16) {
            uint32_t af[2][4], bf[4][4];
            #pragma unroll
            for (int mi = 0; mi < 2; mi++)
                ldsm4t(af[mi], smem_u32(&As[st * KVA_STG +
                    (ks + (quad >> 1) * 8 + r8) * KVA_PITCH + wm + mi * 16 + (quad & 1) * 8]));
            #pragma unroll
            for (int nj = 0; nj < 4; nj++)
                ldsm4t(bf[nj], smem_u32(&Bs[st * KVB_STG +
                    (ks + (quad & 1) * 8 + r8) * KVB_PITCH + wn + nj * 16 + (quad >> 1) * 8]));
            #pragma unroll
            for (int mi = 0; mi < 2; mi++)
                #pragma unroll
                for (int nj = 0; nj < 4; nj++) {
                    mma16816h(accC[mi][2 * nj],     af[mi], &bf[nj][0]);
                    mma16816h(accC[mi][2 * nj + 1], af[mi], &bf[nj][2]);
                }
        }
    }
    int group = lane >> 2, t4 = lane & 3;
    float* dst = &g_kv_part[(size_t)chunk * (4 * DIM * DIM) + h * (DIM * DIM)];
    #pragma unroll
    for (int mi = 0; mi < 2; mi++) {
        int rm = m0 + wm + mi * 16 + group;
        #pragma unroll
        for (int ni = 0; ni < 8; ni++) {
            int c = wn + ni * 8 + t4 * 2;
            float2 a0 = __half22float2(*(__half2*)&accA[mi][ni][0]);
            float2 b0 = __half22float2(*(__half2*)&accB[mi][ni][0]);
            float2 a1 = __half22float2(*(__half2*)&accA[mi][ni][1]);
            float2 b1 = __half22float2(*(__half2*)&accB[mi][ni][1]);
            *(float2*)&dst[rm * 256 + c]       = make_float2(a0.x + b0.x, a0.y + b0.y);
            *(float2*)&dst[(rm + 8) * 256 + c] = make_float2(a1.x + b1.x, a1.y + b1.y);
        }
    }
}

__global__ void kvred_kernel() {
    int i = blockIdx.x * 256 + threadIdx.x;
    float s = 0.f;
    #pragma unroll
    for (int p = 0; p < 16; p++) s += g_kv_part[p * (4 * DIM * DIM) + i];
    g_kvb[i] = __float2half(s);
}

// ------ out = 0.25*((q*invden*65536) @ kv / 65536 + rowoff), K=1024 ----------
#define OAPITCH 72
#define OASTG (128 * OAPITCH)
#define OBSTG (64 * BPITCH)
#define OUT_SMEM_BYTES ((3 * (OASTG + OBSTG)) * 2)

__global__ __launch_bounds__(512) void out_kernel(float* __restrict__ out) {
    extern __shared__ __half sm[];
    __half* As = sm;
    __half* Bs = sm + 3 * OASTG;

    size_t r0 = (size_t)blockIdx.y * 128;
    int tid = threadIdx.x, lane = tid & 31, warp = tid >> 5;
    int wm = (warp & 3) * 32, wn = (warp >> 2) * 64;
    int quad = lane >> 3, r8 = lane & 7;
    int arow = tid >> 3, aseg = tid & 7;
    int brow = tid >> 5, bseg = tid & 31;

    float acc[2][8][4];
    #pragma unroll
    for (int a = 0; a < 2; a++)
        #pragma unroll
        for (int b = 0; b < 8; b++)
            #pragma unroll
            for (int c = 0; c < 4; c++) acc[a][b][c] = 0.f;

    uint4 aR[2];
    float invR[2];

    auto ldgA = [&](int kit) {
        int k0 = kit * 64, h = k0 >> 8;
        #pragma unroll
        for (int rr = 0; rr < 2; rr++) {
            size_t row = r0 + arow + rr * 64;
            aR[rr] = *(const uint4*)&g_q[row * HD + k0 + aseg * 8];
            invR[rr] = g_invden[row * 4 + h];
        }
    };
    auto stsA = [&](int kit) {       // scale by invden*65536 (avoid f16 underflow)
        int st = kit % 3;
        #pragma unroll
        for (int rr = 0; rr < 2; rr++) {
            __half2* p = (__half2*)&aR[rr];
            float iv = invR[rr] * 65536.f;
            uint4 o;
            __half2* q = (__half2*)&o;
            #pragma unroll
            for (int j = 0; j < 4; j++) {
                float2 f = __half22float2(p[j]);
                q[j] = __floats2half2_rn(f.x * iv, f.y * iv);
            }
            *(uint4*)&As[st * OASTG + (arow + rr * 64) * OAPITCH + aseg * 8] = o;
        }
    };
    auto cpB = [&](int kit) {
        int st = kit % 3, k0 = kit * 64;
        #pragma unroll
        for (int rr = 0; rr < 4; rr++)
            cp16(&Bs[st * OBSTG + (brow + rr * 16) * BPITCH + bseg * 8],
                 &g_kvb[(size_t)(k0 + brow + rr * 16) * 256 + bseg * 8]);
        cp_commit();
    };

    ldgA(0); stsA(0);
    ldgA(1);
    cpB(0); cpB(1);
    #pragma unroll 1
    for (int it = 0; it < 16; it++) {
        int st = it % 3;
        if (it < 15) cp_wait<1>(); else cp_wait<0>();
        __syncthreads();
        if (it + 1 < 16) stsA(it + 1);
        if (it + 2 < 16) { ldgA(it + 2); cpB(it + 2); }
        #pragma unroll
        for (int ks = 0; ks < 64; ks += 16) {
            uint32_t af[2][4], bf[4][4];
            #pragma unroll
            for (int mi = 0; mi < 2; mi++)
                ldsm4(af[mi], smem_u32(&As[st * OASTG +
                    (wm + mi * 16 + (quad & 1) * 8 + r8) * OAPITCH + ks + (quad >> 1) * 8]));
            #pragma unroll
            for (int nj = 0; nj < 4; nj++)
                ldsm4t(bf[nj], smem_u32(&Bs[st * OBSTG +
                    (ks + (quad & 1) * 8 + r8) * BPITCH + wn + nj * 16 + (quad >> 1) * 8]));
            #pragma unroll
            for (int mi = 0; mi < 2; mi++)
                #pragma unroll
                for (int nj = 0; nj < 4; nj++) {
                    mma16816f(acc[mi][2 * nj],     af[mi], &bf[nj][0]);
                    mma16816f(acc[mi][2 * nj + 1], af[mi], &bf[nj][2]);
                }
        }
    }

    const float inv64k = 1.f / 65536.f;
    int group = lane >> 2, t4 = lane & 3;
    #pragma unroll
    for (int mi = 0; mi < 2; mi++) {
        size_t rA = r0 + wm + mi * 16 + group;
        size_t rB = rA + 8;
        float ia[4], ib[4];
        #pragma unroll
        for (int h = 0; h < 4; h++) {
            ia[h] = g_invden[rA * 4 + h];
            ib[h] = g_invden[rB * 4 + h];
        }
        #pragma unroll
        for (int ni = 0; ni < 8; ni++) {
            int c = wn + ni * 8 + t4 * 2;
            float roa0 = 0.f, roa1 = 0.f, rob0 = 0.f, rob1 = 0.f;
            #pragma unroll
            for (int h = 0; h < 4; h++) {
                float v0 = __ldg(&g_vsum[h * 256 + c]);
                float v1 = __ldg(&g_vsum[h * 256 + c + 1]);
                roa0 += ia[h] * v0; roa1 += ia[h] * v1;
                rob0 += ib[h] * v0; rob1 += ib[h] * v1;
            }
            *(float2*)&out[rA * 256 + c] =
                make_float2(0.25f * (acc[mi][ni][0] * inv64k + roa0),
                            0.25f * (acc[mi][ni][1] * inv64k + roa1));
            *(float2*)&out[rB * 256 + c] =
                make_float2(0.25f * (acc[mi][ni][2] * inv64k + rob0),
                            0.25f * (acc[mi][ni][3] * inv64k + rob1));
        }
    }
}

// ---------------- launch -----------------------------------------------------
extern "C" void kernel_launch(void* const* d_in, const int* in_sizes, int n_in,
                              void* d_out, int out_size) {
    const float* x  = (const float*)d_in[0];
    const float* Wq = (const float*)d_in[1];
    const float* bq = (const float*)d_in[2];
    const float* Wk = (const float*)d_in[3];
    const float* bk = (const float*)d_in[4];
    const float* Wv = (const float*)d_in[5];
    const float* bv = (const float*)d_in[6];
    float* out = (float*)d_out;

    cudaFuncSetAttribute(qkv_kernel, cudaFuncAttributeMaxDynamicSharedMemorySize, GEMM_SMEM_BYTES);
    cudaFuncSetAttribute(out_kernel, cudaFuncAttributeMaxDynamicSharedMemorySize, OUT_SMEM_BYTES);
    cudaFuncSetAttribute(kv_kernel,  cudaFuncAttributeMaxDynamicSharedMemorySize, KV_SMEM_BYTES);

    cvt_x_kernel<<<256, 256>>>(x);                        // 0
    cvt_w_kernel<<<dim3(512, 3), 256>>>(Wq, Wk, Wv);      // 1
    colsum_red_kernel<<<2, 256>>>();                      // 2
    qkv_kernel<<<dim3(12, 512), 256, GEMM_SMEM_BYTES>>>(bq, bk, bv);   // 3 (profiled)
    vsum_kernel<<<128, 256>>>(Wv, bv);                    // 4
    ksum_red_kernel<<<4, 256>>>();                        // 5
    invden_kernel<<<32768, 256>>>();                      // 6
    kv_kernel<<<dim3(1, 2, 64), 512, KV_SMEM_BYTES>>>();  // 7
    kvred_kernel<<<1024, 256>>>();                        // 8
    out_kernel<<<dim3(1, 512), 512, OUT_SMEM_BYTES>>>(out);  // 9
}

// round 11
// speedup vs baseline: 1.6745x; 1.1176x over previous
#include <cuda_runtime.h>
#include <cuda_fp16.h>
#include <cstdint>

#define NN   65536
#define INC  512
#define HD   1024
#define DIM  256

// ---------------- scratch (device globals) -----------------------------------
__device__ __half g_xh[NN * INC];
__device__ __half g_wh[3][INC * HD];
__device__ __half g_q[NN * HD];
__device__ __half g_k[NN * HD];
__device__ float g_colsum_p[512 * INC];
__device__ float g_colsum[INC];
__device__ float g_vsum[HD];
__device__ float g_ksum_p2[512 * HD];            // per-rowblock col partials of kn
__device__ float g_ksum[HD];
__device__ float g_C_part[16 * HD * INC];        // knT@x split-K partials (32 MB)
__device__ __half g_C[HD * INC];                 // knT@x [hm][k] f16
__device__ __half g_kvb[4 * DIM * DIM];          // kv stacked [h*256+m][d]
__device__ float g_invden[NN * 4];

// ---------------- helpers ----------------------------------------------------
__device__ __forceinline__ uint32_t smem_u32(const void* p) {
    return (uint32_t)__cvta_generic_to_shared(p);
}
__device__ __forceinline__ void ldsm4(uint32_t* r, uint32_t a) {
    asm volatile("ldmatrix.sync.aligned.m8n8.x4.shared.b16 {%0,%1,%2,%3}, [%4];"
        : "=r"(r[0]), "=r"(r[1]), "=r"(r[2]), "=r"(r[3]) : "r"(a));
}
__device__ __forceinline__ void ldsm4t(uint32_t* r, uint32_t a) {
    asm volatile("ldmatrix.sync.aligned.m8n8.x4.trans.shared.b16 {%0,%1,%2,%3}, [%4];"
        : "=r"(r[0]), "=r"(r[1]), "=r"(r[2]), "=r"(r[3]) : "r"(a));
}
// f32 accumulate, f16 inputs
__device__ __forceinline__ void mma16816f(float* d, const uint32_t* a, const uint32_t* b) {
    asm volatile("mma.sync.aligned.m16n8k16.row.col.f32.f16.f16.f32 "
        "{%0,%1,%2,%3}, {%4,%5,%6,%7}, {%8,%9}, {%0,%1,%2,%3};"
        : "+f"(d[0]), "+f"(d[1]), "+f"(d[2]), "+f"(d[3])
        : "r"(a[0]), "r"(a[1]), "r"(a[2]), "r"(a[3]), "r"(b[0]), "r"(b[1]));
}
__device__ __forceinline__ void cp16(void* s, const void* g) {
    asm volatile("cp.async.cg.shared.global [%0], [%1], 16;"
        :: "r"(smem_u32(s)), "l"(g));
}
__device__ __forceinline__ void cp_commit() { asm volatile("cp.async.commit_group;"); }
template<int W> __device__ __forceinline__ void cp_wait() {
    asm volatile("cp.async.wait_group %0;" :: "n"(W));
}

// ---------------- cvt_x + colsum partials (fused) ----------------------------
__global__ void cvt_x_kernel(const float* __restrict__ x) {
    int p = blockIdx.x;                 // 256 blocks, 256 rows each
    int tid = threadIdx.x;              // 256
    int seg = tid & 127, half = tid >> 7;
    size_t r0 = (size_t)p * 256;
    float c0 = 0.f, c1 = 0.f, c2 = 0.f, c3 = 0.f;
    for (int i = half; i < 256; i += 2) {
        float4 f = ((const float4*)x)[(r0 + i) * 128 + seg];
        c0 += f.x; c1 += f.y; c2 += f.z; c3 += f.w;
        __half2* d = (__half2*)g_xh + (r0 + i) * 256 + seg * 2;
        d[0] = __floats2half2_rn(f.x, f.y);
        d[1] = __floats2half2_rn(f.z, f.w);
    }
    float* dst = &g_colsum_p[(p * 2 + half) * INC + seg * 4];
    dst[0] = c0; dst[1] = c1; dst[2] = c2; dst[3] = c3;
}
__global__ void colsum_red_kernel() {
    int c = blockIdx.x * 256 + threadIdx.x;     // grid.x = 2
    float s = 0.f;
    for (int p = 0; p < 512; p++) s += g_colsum_p[p * INC + c];
    g_colsum[c] = s;
}
__global__ void vsum_kernel(const float* __restrict__ Wv, const float* __restrict__ bv) {
    int warp = threadIdx.x >> 5, lane = threadIdx.x & 31;
    int m = blockIdx.x * 8 + warp;               // grid = 128
    float s = 0.f;
    for (int kk = lane; kk < INC; kk += 32) s += g_colsum[kk] * Wv[kk * HD + m];
    #pragma unroll
    for (int o = 16; o > 0; o >>= 1) s += __shfl_xor_sync(0xffffffffu, s, o);
    if (lane == 0) g_vsum[m] = s + 65536.f * bv[m];
}

__global__ void cvt_w_kernel(const float* __restrict__ Wq,
                             const float* __restrict__ Wk,
                             const float* __restrict__ Wv) {
    int which = blockIdx.y;
    const float* src = which == 0 ? Wq : which == 1 ? Wk : Wv;
    int i = blockIdx.x * 256 + threadIdx.x;      // grid.x = 512
    float4 f = ((const float4*)src)[i];
    __half2* d2 = (__half2*)g_wh[which];
    d2[2 * i]     = __floats2half2_rn(f.x, f.y);
    d2[2 * i + 1] = __floats2half2_rn(f.z, f.w);
}

// ---------------- fused q,k GEMM + bias + L2-normalize + ksum ----------------
#define APITCH 72
#define BPITCH 264
#define ASTG (128 * APITCH)
#define BSTG (64 * BPITCH)
#define GEMM_SMEM_BYTES ((3 * (ASTG + BSTG)) * 2)

__global__ __launch_bounds__(256) void qk_kernel(const float* __restrict__ bq,
                                                 const float* __restrict__ bk) {
    extern __shared__ __half sm[];
    char* smc = (char*)sm;
    __half* As = sm;                  // [3][128][APITCH]
    __half* Bs = sm + 3 * ASTG;       // [3][64][BPITCH]

    int which = blockIdx.x >> 2;
    int n0 = (blockIdx.x & 3) * 256;
    size_t r0 = (size_t)blockIdx.y * 128;
    const __half* __restrict__ B = g_wh[which];
    __half* __restrict__ C = which == 0 ? g_q : g_k;
    const float* __restrict__ bias = which == 0 ? bq : bk;

    int tid = threadIdx.x, lane = tid & 31, warp = tid >> 5;
    int wm = (warp & 1) * 64, wn = (warp >> 1) * 64;
    int quad = lane >> 3, r8 = lane & 7;
    int arow = tid >> 3, aseg = tid & 7;
    int brow = tid >> 5, bseg = tid & 31;

    float acc[4][8][4];
    #pragma unroll
    for (int a = 0; a < 4; a++)
        #pragma unroll
        for (int b = 0; b < 8; b++)
            #pragma unroll
            for (int c = 0; c < 4; c++) acc[a][b][c] = 0.f;

    auto load_stage = [&](int st, int k0) {
        #pragma unroll
        for (int rr = 0; rr < 4; rr++)
            cp16(&As[st * ASTG + (arow + rr * 32) * APITCH + aseg * 8],
                 &g_xh[(r0 + arow + rr * 32) * INC + k0 + aseg * 8]);
        #pragma unroll
        for (int rr = 0; rr < 8; rr++)
            cp16(&Bs[st * BSTG + (brow + rr * 8) * BPITCH + bseg * 8],
                 &B[(size_t)(k0 + brow + rr * 8) * HD + n0 + bseg * 8]);
        cp_commit();
    };

    load_stage(0, 0);
    load_stage(1, 64);
    #pragma unroll 1
    for (int it = 0; it < 8; it++) {
        int st = it % 3;
        if (it < 7) cp_wait<1>(); else cp_wait<0>();
        __syncthreads();
        if (it + 2 < 8) load_stage((it + 2) % 3, (it + 2) * 64);
        #pragma unroll
        for (int ks = 0; ks < 64; ks += 16) {
            uint32_t af[4][4], bf[4][4];
            #pragma unroll
            for (int mi = 0; mi < 4; mi++)
                ldsm4(af[mi], smem_u32(&As[st * ASTG +
                    (wm + mi * 16 + (quad & 1) * 8 + r8) * APITCH + ks + (quad >> 1) * 8]));
            #pragma unroll
            for (int nj = 0; nj < 4; nj++)
                ldsm4t(bf[nj], smem_u32(&Bs[st * BSTG +
                    (ks + (quad & 1) * 8 + r8) * BPITCH + wn + nj * 16 + (quad >> 1) * 8]));
            #pragma unroll
            for (int mi = 0; mi < 4; mi++)
                #pragma unroll
                for (int nj = 0; nj < 4; nj++) {
                    mma16816f(acc[mi][2 * nj],     af[mi], &bf[nj][0]);
                    mma16816f(acc[mi][2 * nj + 1], af[mi], &bf[nj][2]);
                }
        }
    }

    int group = lane >> 2, t4 = lane & 3;
    float ss0[4] = {0.f, 0.f, 0.f, 0.f}, ss1[4] = {0.f, 0.f, 0.f, 0.f};
    #pragma unroll
    for (int mi = 0; mi < 4; mi++)
        #pragma unroll
        for (int ni = 0; ni < 8; ni++) {
            int c = n0 + wn + ni * 8 + t4 * 2;
            float b0 = __ldg(&bias[c]), b1 = __ldg(&bias[c + 1]);
            acc[mi][ni][0] += b0; acc[mi][ni][1] += b1;
            acc[mi][ni][2] += b0; acc[mi][ni][3] += b1;
            ss0[mi] += acc[mi][ni][0] * acc[mi][ni][0] + acc[mi][ni][1] * acc[mi][ni][1];
            ss1[mi] += acc[mi][ni][2] * acc[mi][ni][2] + acc[mi][ni][3] * acc[mi][ni][3];
        }

    // L2 normalize (tile n-range == one full head)
    #pragma unroll
    for (int mi = 0; mi < 4; mi++) {
        ss0[mi] += __shfl_xor_sync(0xffffffffu, ss0[mi], 1);
        ss0[mi] += __shfl_xor_sync(0xffffffffu, ss0[mi], 2);
        ss1[mi] += __shfl_xor_sync(0xffffffffu, ss1[mi], 1);
        ss1[mi] += __shfl_xor_sync(0xffffffffu, ss1[mi], 2);
    }
    float* ssbuf = (float*)smc;
    int wng = warp >> 1;
    if (t4 == 0) {
        #pragma unroll
        for (int mi = 0; mi < 4; mi++) {
            ssbuf[wng * 128 + wm + mi * 16 + group]     = ss0[mi];
            ssbuf[wng * 128 + wm + mi * 16 + group + 8] = ss1[mi];
        }
    }
    __syncthreads();
    #pragma unroll
    for (int mi = 0; mi < 4; mi++) {
        int ra = wm + mi * 16 + group;
        float s0 = ssbuf[ra] + ssbuf[128 + ra] + ssbuf[256 + ra] + ssbuf[384 + ra];
        int rb = ra + 8;
        float s1 = ssbuf[rb] + ssbuf[128 + rb] + ssbuf[256 + rb] + ssbuf[384 + rb];
        float i0 = rsqrtf(s0), i1 = rsqrtf(s1);
        #pragma unroll
        for (int ni = 0; ni < 8; ni++) {
            acc[mi][ni][0] *= i0; acc[mi][ni][1] *= i0;
            acc[mi][ni][2] *= i1; acc[mi][ni][3] *= i1;
        }
    }

    #pragma unroll
    for (int mi = 0; mi < 4; mi++) {
        size_t rA = r0 + wm + mi * 16 + group;
        #pragma unroll
        for (int ni = 0; ni < 8; ni++) {
            int c = n0 + wn + ni * 8 + t4 * 2;
            *(__half2*)&C[rA * HD + c] =
                __floats2half2_rn(acc[mi][ni][0], acc[mi][ni][1]);
            *(__half2*)&C[(rA + 8) * HD + c] =
                __floats2half2_rn(acc[mi][ni][2], acc[mi][ni][3]);
        }
    }

    // fused ksum partials: column sums of this 128x256 kn tile
    if (which == 1) {
        float cs[8][2];
        #pragma unroll
        for (int ni = 0; ni < 8; ni++) {
            cs[ni][0] = 0.f; cs[ni][1] = 0.f;
            #pragma unroll
            for (int mi = 0; mi < 4; mi++) {
                cs[ni][0] += acc[mi][ni][0] + acc[mi][ni][2];
                cs[ni][1] += acc[mi][ni][1] + acc[mi][ni][3];
            }
            #pragma unroll
            for (int o = 4; o < 32; o <<= 1) {
                cs[ni][0] += __shfl_xor_sync(0xffffffffu, cs[ni][0], o);
                cs[ni][1] += __shfl_xor_sync(0xffffffffu, cs[ni][1], o);
            }
        }
        __syncthreads();
        float* cbuf = (float*)smc;
        if (lane < 4) {
            #pragma unroll
            for (int ni = 0; ni < 8; ni++) {
                cbuf[warp * 64 + ni * 8 + lane * 2]     = cs[ni][0];
                cbuf[warp * 64 + ni * 8 + lane * 2 + 1] = cs[ni][1];
            }
        }
        __syncthreads();
        int g2 = tid >> 6, cc = tid & 63;
        float s = cbuf[(2 * g2) * 64 + cc] + cbuf[(2 * g2 + 1) * 64 + cc];
        g_ksum_p2[blockIdx.y * HD + n0 + g2 * 64 + cc] = s;
    }
}

// ---------------- ksum final reduce ------------------------------------------
__global__ void ksum_red_kernel() {
    int c = blockIdx.x * 256 + threadIdx.x;   // grid.x = 4
    float s = 0.f;
    for (int p = 0; p < 512; p++) s += g_ksum_p2[p * HD + c];
    g_ksum[c] = s;
}

// ---------------- invden[n,h] = 1/(qn . ksum[h] + N) -------------------------
__global__ void invden_kernel() {
    int wg = blockIdx.x * 8 + (threadIdx.x >> 5);   // wg = n*4+h
    int lane = threadIdx.x & 31, h = wg & 3;
    size_t base = (size_t)wg * 256 + lane * 8;
    uint4 raw = *(const uint4*)&g_q[base];
    __half2* p = (__half2*)&raw;
    const float* ks = &g_ksum[h * 256 + lane * 8];
    float s = 0.f;
    #pragma unroll
    for (int i = 0; i < 4; i++) {
        float2 f = __half22float2(p[i]);
        s += f.x * ks[2 * i] + f.y * ks[2 * i + 1];
    }
    #pragma unroll
    for (int o = 16; o > 0; o >>= 1) s += __shfl_xor_sync(0xffffffffu, s, o);
    if (lane == 0) g_invden[wg] = 1.f / (s + 65536.f);
}

// ---------------- C = kn^T @ x : [1024, 512], split-K over n -----------------
#define CA_PITCH 136
#define CB_PITCH 264
#define CA_STG (64 * CA_PITCH)
#define CB_STG (64 * CB_PITCH)
#define C_SMEM_BYTES ((3 * (CA_STG + CB_STG)) * 2)

__global__ __launch_bounds__(256) void c_kernel() {
    extern __shared__ __half sm[];
    __half* As = sm;                   // [3][64 n][CA_PITCH]  kn[n][m-slice]
    __half* Bs = sm + 3 * CA_STG;      // [3][64 n][CB_PITCH]  x[n][j-slice]

    int tid = threadIdx.x, lane = tid & 31, warp = tid >> 5;
    int wm = (warp & 1) * 64, wn = (warp >> 1) * 64;
    int m0 = blockIdx.x * 128;                   // grid.x = 8
    int j0 = blockIdx.y * 256;                   // grid.y = 2
    int chunk = blockIdx.z;                      // grid.z = 16
    size_t n0 = (size_t)chunk * 4096;
    int quad = lane >> 3, r8 = lane & 7;
    int arow = tid >> 4, aseg = tid & 15;
    int brow = tid >> 5, bseg = tid & 31;

    float acc[4][8][4];
    #pragma unroll
    for (int a = 0; a < 4; a++)
        #pragma unroll
        for (int b = 0; b < 8; b++)
            #pragma unroll
            for (int c = 0; c < 4; c++) acc[a][b][c] = 0.f;

    auto load_stage = [&](int st, int kk) {
        #pragma unroll
        for (int rr = 0; rr < 4; rr++)
            cp16(&As[st * CA_STG + (arow + rr * 16) * CA_PITCH + aseg * 8],
                 &g_k[(n0 + kk + arow + rr * 16) * HD + m0 + aseg * 8]);
        #pragma unroll
        for (int rr = 0; rr < 8; rr++)
            cp16(&Bs[st * CB_STG + (brow + rr * 8) * CB_PITCH + bseg * 8],
                 &g_xh[(n0 + kk + brow + rr * 8) * INC + j0 + bseg * 8]);
        cp_commit();
    };

    load_stage(0, 0);
    load_stage(1, 64);
    #pragma unroll 1
    for (int it = 0; it < 64; it++) {
        int st = it % 3;
        if (it < 63) cp_wait<1>(); else cp_wait<0>();
        __syncthreads();
        if (it + 2 < 64) load_stage((it + 2) % 3, (it + 2) * 64);
        #pragma unroll
        for (int ks = 0; ks < 64; ks += 16) {
            uint32_t af[4][4], bf[4][4];
            #pragma unroll
            for (int mi = 0; mi < 4; mi++)
                ldsm4t(af[mi], smem_u32(&As[st * CA_STG +
                    (ks + (quad >> 1) * 8 + r8) * CA_PITCH + wm + mi * 16 + (quad & 1) * 8]));
            #pragma unroll
            for (int nj = 0; nj < 4; nj++)
                ldsm4t(bf[nj], smem_u32(&Bs[st * CB_STG +
                    (ks + (quad & 1) * 8 + r8) * CB_PITCH + wn + nj * 16 + (quad >> 1) * 8]));
            #pragma unroll
            for (int mi = 0; mi < 4; mi++)
                #pragma unroll
                for (int nj = 0; nj < 4; nj++) {
                    mma16816f(acc[mi][2 * nj],     af[mi], &bf[nj][0]);
                    mma16816f(acc[mi][2 * nj + 1], af[mi], &bf[nj][2]);
                }
        }
    }
    int group = lane >> 2, t4 = lane & 3;
    float* dst = &g_C_part[(size_t)chunk * (HD * INC)];
    #pragma unroll
    for (int mi = 0; mi < 4; mi++) {
        int rm = m0 + wm + mi * 16 + group;
        #pragma unroll
        for (int ni = 0; ni < 8; ni++) {
            int c = j0 + wn + ni * 8 + t4 * 2;
            *(float2*)&dst[rm * INC + c]       = make_float2(acc[mi][ni][0], acc[mi][ni][1]);
            *(float2*)&dst[(rm + 8) * INC + c] = make_float2(acc[mi][ni][2], acc[mi][ni][3]);
        }
    }
}

__global__ void cred_kernel() {
    int i = blockIdx.x * 256 + threadIdx.x;      // grid = 2048
    float s = 0.f;
    #pragma unroll
    for (int p = 0; p < 16; p++) s += g_C_part[(size_t)p * (HD * INC) + i];
    g_C[i] = __float2half(s);
}

// -------- kv_h = C_h @ Wv_h + ksum_h (x) bv_h : [4][256][256] -> f16 ---------
__global__ __launch_bounds__(256) void kvsmall_kernel(const float* __restrict__ bv) {
    __shared__ __half As[128][72];    // C tile [m][k64]
    __shared__ __half Bs[64][136];    // Wv tile [k64][d128]
    int h = blockIdx.z;
    int m0 = blockIdx.x * 128;                   // within head
    int d0 = blockIdx.y * 128;
    int tid = threadIdx.x, lane = tid & 31, warp = tid >> 5;
    int wm = (warp & 1) * 64, wn = (warp >> 1) * 32;   // 2 m x 4 n groups (32 each)
    int quad = lane >> 3, r8 = lane & 7;
    int arow = tid >> 3, aseg = tid & 7;
    int brow = tid >> 4, bseg = tid & 15;

    float acc[4][4][4];
    #pragma unroll
    for (int a = 0; a < 4; a++)
        #pragma unroll
        for (int b = 0; b < 4; b++)
            #pragma unroll
            for (int c = 0; c < 4; c++) acc[a][b][c] = 0.f;

    #pragma unroll 1
    for (int kt = 0; kt < 8; kt++) {
        int k0 = kt * 64;
        __syncthreads();
        #pragma unroll
        for (int rr = 0; rr < 4; rr++)
            *(uint4*)&As[arow + rr * 32][aseg * 8] =
                *(const uint4*)&g_C[(size_t)(h * 256 + m0 + arow + rr * 32) * INC + k0 + aseg * 8];
        #pragma unroll
        for (int rr = 0; rr < 4; rr++)
            *(uint4*)&Bs[brow + rr * 16][bseg * 8] =
                *(const uint4*)&g_wh[2][(size_t)(k0 + brow + rr * 16) * HD + h * 256 + d0 + bseg * 8];
        __syncthreads();
        #pragma unroll
        for (int ks = 0; ks < 64; ks += 16) {
            uint32_t af[4][4], bf[2][4];
            #pragma unroll
            for (int mi = 0; mi < 4; mi++)
                ldsm4(af[mi], smem_u32(&As[wm + mi * 16 + (quad & 1) * 8 + r8][ks + (quad >> 1) * 8]));
            #pragma unroll
            for (int nj = 0; nj < 2; nj++)
                ldsm4t(bf[nj], smem_u32(&Bs[ks + (quad & 1) * 8 + r8][wn + nj * 16 + (quad >> 1) * 8]));
            #pragma unroll
            for (int mi = 0; mi < 4; mi++)
                #pragma unroll
                for (int nj = 0; nj < 2; nj++) {
                    mma16816f(acc[mi][2 * nj],     af[mi], &bf[nj][0]);
                    mma16816f(acc[mi][2 * nj + 1], af[mi], &bf[nj][2]);
                }
        }
    }

    int group = lane >> 2, t4 = lane & 3;
    #pragma unroll
    for (int mi = 0; mi < 4; mi++) {
        int rm = m0 + wm + mi * 16 + group;         // within head
        float ksA = g_ksum[h * 256 + rm], ksB = g_ksum[h * 256 + rm + 8];
        #pragma unroll
        for (int ni = 0; ni < 4; ni++) {
            int c = d0 + wn + ni * 8 + t4 * 2;
            float b0 = __ldg(&bv[h * 256 + c]), b1 = __ldg(&bv[h * 256 + c + 1]);
            *(__half2*)&g_kvb[(size_t)(h * 256 + rm) * 256 + c] =
                __floats2half2_rn(acc[mi][ni][0] + ksA * b0, acc[mi][ni][1] + ksA * b1);
            *(__half2*)&g_kvb[(size_t)(h * 256 + rm + 8) * 256 + c] =
                __floats2half2_rn(acc[mi][ni][2] + ksB * b0, acc[mi][ni][3] + ksB * b1);
        }
    }
}

// ------ out = 0.25*((q*invden*65536) @ kv / 65536 + rowoff), K=1024 ----------
#define OAPITCH 72
#define OASTG (128 * OAPITCH)
#define OBSTG (64 * BPITCH)
#define OUT_SMEM_BYTES ((3 * (OASTG + OBSTG)) * 2)

__global__ __launch_bounds__(512) void out_kernel(float* __restrict__ out) {
    extern __shared__ __half sm[];
    __half* As = sm;
    __half* Bs = sm + 3 * OASTG;

    size_t r0 = (size_t)blockIdx.y * 128;
    int tid = threadIdx.x, lane = tid & 31, warp = tid >> 5;
    int wm = (warp & 3) * 32, wn = (warp >> 2) * 64;
    int quad = lane >> 3, r8 = lane & 7;
    int arow = tid >> 3, aseg = tid & 7;
    int brow = tid >> 5, bseg = tid & 31;

    float acc[2][8][4];
    #pragma unroll
    for (int a = 0; a < 2; a++)
        #pragma unroll
        for (int b = 0; b < 8; b++)
            #pragma unroll
            for (int c = 0; c < 4; c++) acc[a][b][c] = 0.f;

    uint4 aR[2];
    float invR[2];

    auto ldgA = [&](int kit) {
        int k0 = kit * 64, h = k0 >> 8;
        #pragma unroll
        for (int rr = 0; rr < 2; rr++) {
            size_t row = r0 + arow + rr * 64;
            aR[rr] = *(const uint4*)&g_q[row * HD + k0 + aseg * 8];
            invR[rr] = g_invden[row * 4 + h];
        }
    };
    auto stsA = [&](int kit) {
        int st = kit % 3;
        #pragma unroll
        for (int rr = 0; rr < 2; rr++) {
            __half2* p = (__half2*)&aR[rr];
            float iv = invR[rr] * 65536.f;
            uint4 o;
            __half2* q = (__half2*)&o;
            #pragma unroll
            for (int j = 0; j < 4; j++) {
                float2 f = __half22float2(p[j]);
                q[j] = __floats2half2_rn(f.x * iv, f.y * iv);
            }
            *(uint4*)&As[st * OASTG + (arow + rr * 64) * OAPITCH + aseg * 8] = o;
        }
    };
    auto cpB = [&](int kit) {
        int st = kit % 3, k0 = kit * 64;
        #pragma unroll
        for (int rr = 0; rr < 4; rr++)
            cp16(&Bs[st * OBSTG + (brow + rr * 16) * BPITCH + bseg * 8],
                 &g_kvb[(size_t)(k0 + brow + rr * 16) * 256 + bseg * 8]);
        cp_commit();
    };

    ldgA(0); stsA(0);
    ldgA(1);
    cpB(0); cpB(1);
    #pragma unroll 1
    for (int it = 0; it < 16; it++) {
        int st = it % 3;
        if (it < 15) cp_wait<1>(); else cp_wait<0>();
        __syncthreads();
        if (it + 1 < 16) stsA(it + 1);
        if (it + 2 < 16) { ldgA(it + 2); cpB(it + 2); }
        #pragma unroll
        for (int ks = 0; ks < 64; ks += 16) {
            uint32_t af[2][4], bf[4][4];
            #pragma unroll
            for (int mi = 0; mi < 2; mi++)
                ldsm4(af[mi], smem_u32(&As[st * OASTG +
                    (wm + mi * 16 + (quad & 1) * 8 + r8) * OAPITCH + ks + (quad >> 1) * 8]));
            #pragma unroll
            for (int nj = 0; nj < 4; nj++)
                ldsm4t(bf[nj], smem_u32(&Bs[st * OBSTG +
                    (ks + (quad & 1) * 8 + r8) * BPITCH + wn + nj * 16 + (quad >> 1) * 8]));
            #pragma unroll
            for (int mi = 0; mi < 2; mi++)
                #pragma unroll
                for (int nj = 0; nj < 4; nj++) {
                    mma16816f(acc[mi][2 * nj],     af[mi], &bf[nj][0]);
                    mma16816f(acc[mi][2 * nj + 1], af[mi], &bf[nj][2]);
                }
        }
    }

    const float inv64k = 1.f / 65536.f;
    int group = lane >> 2, t4 = lane & 3;
    #pragma unroll
    for (int mi = 0; mi < 2; mi++) {
        size_t rA = r0 + wm + mi * 16 + group;
        size_t rB = rA + 8;
        float ia[4], ib[4];
        #pragma unroll
        for (int h = 0; h < 4; h++) {
            ia[h] = g_invden[rA * 4 + h];
            ib[h] = g_invden[rB * 4 + h];
        }
        #pragma unroll
        for (int ni = 0; ni < 8; ni++) {
            int c = wn + ni * 8 + t4 * 2;
            float roa0 = 0.f, roa1 = 0.f, rob0 = 0.f, rob1 = 0.f;
            #pragma unroll
            for (int h = 0; h < 4; h++) {
                float v0 = __ldg(&g_vsum[h * 256 + c]);
                float v1 = __ldg(&g_vsum[h * 256 + c + 1]);
                roa0 += ia[h] * v0; roa1 += ia[h] * v1;
                rob0 += ib[h] * v0; rob1 += ib[h] * v1;
            }
            *(float2*)&out[rA * 256 + c] =
                make_float2(0.25f * (acc[mi][ni][0] * inv64k + roa0),
                            0.25f * (acc[mi][ni][1] * inv64k + roa1));
            *(float2*)&out[rB * 256 + c] =
                make_float2(0.25f * (acc[mi][ni][2] * inv64k + rob0),
                            0.25f * (acc[mi][ni][3] * inv64k + rob1));
        }
    }
}

// ---------------- launch -----------------------------------------------------
extern "C" void kernel_launch(void* const* d_in, const int* in_sizes, int n_in,
                              void* d_out, int out_size) {
    const float* x  = (const float*)d_in[0];
    const float* Wq = (const float*)d_in[1];
    const float* bq = (const float*)d_in[2];
    const float* Wk = (const float*)d_in[3];
    const float* bk = (const float*)d_in[4];
    const float* Wv = (const float*)d_in[5];
    const float* bv = (const float*)d_in[6];
    float* out = (float*)d_out;

    cudaFuncSetAttribute(qk_kernel,  cudaFuncAttributeMaxDynamicSharedMemorySize, GEMM_SMEM_BYTES);
    cudaFuncSetAttribute(c_kernel,   cudaFuncAttributeMaxDynamicSharedMemorySize, C_SMEM_BYTES);
    cudaFuncSetAttribute(out_kernel, cudaFuncAttributeMaxDynamicSharedMemorySize, OUT_SMEM_BYTES);

    cvt_x_kernel<<<256, 256>>>(x);                        // 0
    cvt_w_kernel<<<dim3(512, 3), 256>>>(Wq, Wk, Wv);      // 1
    colsum_red_kernel<<<2, 256>>>();                      // 2
    qk_kernel<<<dim3(8, 512), 256, GEMM_SMEM_BYTES>>>(bq, bk);   // 3 (profiled)
    vsum_kernel<<<128, 256>>>(Wv, bv);                    // 4
    ksum_red_kernel<<<4, 256>>>();                        // 5
    invden_kernel<<<32768, 256>>>();                      // 6
    c_kernel<<<dim3(8, 2, 16), 256, C_SMEM_BYTES>>>();    // 7
    cred_kernel<<<2048, 256>>>();                         // 8
    kvsmall_kernel<<<dim3(2, 2, 4), 256>>>(bv);           // 9
    out_kernel<<<dim3(1, 512), 512, OUT_SMEM_BYTES>>>(out);  // 10
}

// round 12
// speedup vs baseline: 1.8222x; 1.0882x over previous
#include <cuda_runtime.h>
#include <cuda_fp16.h>
#include <cstdint>

#define NN   65536
#define INC  512
#define HD   1024
#define DIM  256

// ---------------- scratch (device globals) -----------------------------------
__device__ __half g_xh[NN * INC];
__device__ __half g_wh[3][INC * HD];
__device__ __half g_q[NN * HD];
__device__ __half g_k[NN * HD];
__device__ float g_colsum_p[512 * INC];
__device__ float g_colsum[INC];
__device__ float g_vsum[HD];
__device__ float g_ksum_p2[512 * HD];
__device__ float g_ksum[HD];
__device__ float g_C_part[9 * HD * INC];         // knT@x split-K partials (18 MB)
__device__ __half g_C[HD * INC];                 // knT@x [hm][k] f16
__device__ __half g_kvb[4 * DIM * DIM];          // kv stacked [h*256+m][d]
__device__ float g_invden[NN * 4];

// ---------------- helpers ----------------------------------------------------
__device__ __forceinline__ uint32_t smem_u32(const void* p) {
    return (uint32_t)__cvta_generic_to_shared(p);
}
__device__ __forceinline__ void ldsm4(uint32_t* r, uint32_t a) {
    asm volatile("ldmatrix.sync.aligned.m8n8.x4.shared.b16 {%0,%1,%2,%3}, [%4];"
        : "=r"(r[0]), "=r"(r[1]), "=r"(r[2]), "=r"(r[3]) : "r"(a));
}
__device__ __forceinline__ void ldsm4t(uint32_t* r, uint32_t a) {
    asm volatile("ldmatrix.sync.aligned.m8n8.x4.trans.shared.b16 {%0,%1,%2,%3}, [%4];"
        : "=r"(r[0]), "=r"(r[1]), "=r"(r[2]), "=r"(r[3]) : "r"(a));
}
__device__ __forceinline__ void mma16816f(float* d, const uint32_t* a, const uint32_t* b) {
    asm volatile("mma.sync.aligned.m16n8k16.row.col.f32.f16.f16.f32 "
        "{%0,%1,%2,%3}, {%4,%5,%6,%7}, {%8,%9}, {%0,%1,%2,%3};"
        : "+f"(d[0]), "+f"(d[1]), "+f"(d[2]), "+f"(d[3])
        : "r"(a[0]), "r"(a[1]), "r"(a[2]), "r"(a[3]), "r"(b[0]), "r"(b[1]));
}
__device__ __forceinline__ void cp16(void* s, const void* g) {
    asm volatile("cp.async.cg.shared.global [%0], [%1], 16;"
        :: "r"(smem_u32(s)), "l"(g));
}
__device__ __forceinline__ void cp_commit() { asm volatile("cp.async.commit_group;"); }
template<int W> __device__ __forceinline__ void cp_wait() {
    asm volatile("cp.async.wait_group %0;" :: "n"(W));
}

// ---------------- cvt_x + colsum partials (fused) ----------------------------
__global__ void cvt_x_kernel(const float* __restrict__ x) {
    int p = blockIdx.x;                 // 256 blocks, 256 rows each
    int tid = threadIdx.x;              // 256
    int seg = tid & 127, half = tid >> 7;
    size_t r0 = (size_t)p * 256;
    float c0 = 0.f, c1 = 0.f, c2 = 0.f, c3 = 0.f;
    for (int i = half; i < 256; i += 2) {
        float4 f = ((const float4*)x)[(r0 + i) * 128 + seg];
        c0 += f.x; c1 += f.y; c2 += f.z; c3 += f.w;
        __half2* d = (__half2*)g_xh + (r0 + i) * 256 + seg * 2;
        d[0] = __floats2half2_rn(f.x, f.y);
        d[1] = __floats2half2_rn(f.z, f.w);
    }
    float* dst = &g_colsum_p[(p * 2 + half) * INC + seg * 4];
    dst[0] = c0; dst[1] = c1; dst[2] = c2; dst[3] = c3;
}
__global__ void colsum_red_kernel() {
    int c = blockIdx.x * 256 + threadIdx.x;     // grid.x = 2
    float s = 0.f;
    for (int p = 0; p < 512; p++) s += g_colsum_p[p * INC + c];
    g_colsum[c] = s;
}
__global__ void vsum_kernel(const float* __restrict__ Wv, const float* __restrict__ bv) {
    int warp = threadIdx.x >> 5, lane = threadIdx.x & 31;
    int m = blockIdx.x * 8 + warp;               // grid = 128
    float s = 0.f;
    for (int kk = lane; kk < INC; kk += 32) s += g_colsum[kk] * Wv[kk * HD + m];
    #pragma unroll
    for (int o = 16; o > 0; o >>= 1) s += __shfl_xor_sync(0xffffffffu, s, o);
    if (lane == 0) g_vsum[m] = s + 65536.f * bv[m];
}

__global__ void cvt_w_kernel(const float* __restrict__ Wq,
                             const float* __restrict__ Wk,
                             const float* __restrict__ Wv) {
    int which = blockIdx.y;
    const float* src = which == 0 ? Wq : which == 1 ? Wk : Wv;
    int i = blockIdx.x * 256 + threadIdx.x;      // grid.x = 512
    float4 f = ((const float4*)src)[i];
    __half2* d2 = (__half2*)g_wh[which];
    d2[2 * i]     = __floats2half2_rn(f.x, f.y);
    d2[2 * i + 1] = __floats2half2_rn(f.z, f.w);
}

// ---------------- fused q,k GEMM + bias + L2-normalize + ksum ----------------
#define APITCH 72
#define BPITCH 264
#define ASTG (128 * APITCH)
#define BSTG (64 * BPITCH)
#define GEMM_SMEM_BYTES ((3 * (ASTG + BSTG)) * 2)

__global__ __launch_bounds__(256) void qk_kernel(const float* __restrict__ bq,
                                                 const float* __restrict__ bk) {
    extern __shared__ __half sm[];
    char* smc = (char*)sm;
    __half* As = sm;
    __half* Bs = sm + 3 * ASTG;

    int which = blockIdx.x >> 2;
    int n0 = (blockIdx.x & 3) * 256;
    size_t r0 = (size_t)blockIdx.y * 128;
    const __half* __restrict__ B = g_wh[which];
    __half* __restrict__ C = which == 0 ? g_q : g_k;
    const float* __restrict__ bias = which == 0 ? bq : bk;

    int tid = threadIdx.x, lane = tid & 31, warp = tid >> 5;
    int wm = (warp & 1) * 64, wn = (warp >> 1) * 64;
    int quad = lane >> 3, r8 = lane & 7;
    int arow = tid >> 3, aseg = tid & 7;
    int brow = tid >> 5, bseg = tid & 31;

    float acc[4][8][4];
    #pragma unroll
    for (int a = 0; a < 4; a++)
        #pragma unroll
        for (int b = 0; b < 8; b++)
            #pragma unroll
            for (int c = 0; c < 4; c++) acc[a][b][c] = 0.f;

    auto load_stage = [&](int st, int k0) {
        #pragma unroll
        for (int rr = 0; rr < 4; rr++)
            cp16(&As[st * ASTG + (arow + rr * 32) * APITCH + aseg * 8],
                 &g_xh[(r0 + arow + rr * 32) * INC + k0 + aseg * 8]);
        #pragma unroll
        for (int rr = 0; rr < 8; rr++)
            cp16(&Bs[st * BSTG + (brow + rr * 8) * BPITCH + bseg * 8],
                 &B[(size_t)(k0 + brow + rr * 8) * HD + n0 + bseg * 8]);
        cp_commit();
    };

    load_stage(0, 0);
    load_stage(1, 64);
    #pragma unroll 1
    for (int it = 0; it < 8; it++) {
        int st = it % 3;
        if (it < 7) cp_wait<1>(); else cp_wait<0>();
        __syncthreads();
        if (it + 2 < 8) load_stage((it + 2) % 3, (it + 2) * 64);
        #pragma unroll
        for (int ks = 0; ks < 64; ks += 16) {
            uint32_t af[4][4], bf[4][4];
            #pragma unroll
            for (int mi = 0; mi < 4; mi++)
                ldsm4(af[mi], smem_u32(&As[st * ASTG +
                    (wm + mi * 16 + (quad & 1) * 8 + r8) * APITCH + ks + (quad >> 1) * 8]));
            #pragma unroll
            for (int nj = 0; nj < 4; nj++)
                ldsm4t(bf[nj], smem_u32(&Bs[st * BSTG +
                    (ks + (quad & 1) * 8 + r8) * BPITCH + wn + nj * 16 + (quad >> 1) * 8]));
            #pragma unroll
            for (int mi = 0; mi < 4; mi++)
                #pragma unroll
                for (int nj = 0; nj < 4; nj++) {
                    mma16816f(acc[mi][2 * nj],     af[mi], &bf[nj][0]);
                    mma16816f(acc[mi][2 * nj + 1], af[mi], &bf[nj][2]);
                }
        }
    }

    int group = lane >> 2, t4 = lane & 3;
    float ss0[4] = {0.f, 0.f, 0.f, 0.f}, ss1[4] = {0.f, 0.f, 0.f, 0.f};
    #pragma unroll
    for (int mi = 0; mi < 4; mi++)
        #pragma unroll
        for (int ni = 0; ni < 8; ni++) {
            int c = n0 + wn + ni * 8 + t4 * 2;
            float b0 = __ldg(&bias[c]), b1 = __ldg(&bias[c + 1]);
            acc[mi][ni][0] += b0; acc[mi][ni][1] += b1;
            acc[mi][ni][2] += b0; acc[mi][ni][3] += b1;
            ss0[mi] += acc[mi][ni][0] * acc[mi][ni][0] + acc[mi][ni][1] * acc[mi][ni][1];
            ss1[mi] += acc[mi][ni][2] * acc[mi][ni][2] + acc[mi][ni][3] * acc[mi][ni][3];
        }

    #pragma unroll
    for (int mi = 0; mi < 4; mi++) {
        ss0[mi] += __shfl_xor_sync(0xffffffffu, ss0[mi], 1);
        ss0[mi] += __shfl_xor_sync(0xffffffffu, ss0[mi], 2);
        ss1[mi] += __shfl_xor_sync(0xffffffffu, ss1[mi], 1);
        ss1[mi] += __shfl_xor_sync(0xffffffffu, ss1[mi], 2);
    }
    float* ssbuf = (float*)smc;
    int wng = warp >> 1;
    if (t4 == 0) {
        #pragma unroll
        for (int mi = 0; mi < 4; mi++) {
            ssbuf[wng * 128 + wm + mi * 16 + group]     = ss0[mi];
            ssbuf[wng * 128 + wm + mi * 16 + group + 8] = ss1[mi];
        }
    }
    __syncthreads();
    #pragma unroll
    for (int mi = 0; mi < 4; mi++) {
        int ra = wm + mi * 16 + group;
        float s0 = ssbuf[ra] + ssbuf[128 + ra] + ssbuf[256 + ra] + ssbuf[384 + ra];
        int rb = ra + 8;
        float s1 = ssbuf[rb] + ssbuf[128 + rb] + ssbuf[256 + rb] + ssbuf[384 + rb];
        float i0 = rsqrtf(s0), i1 = rsqrtf(s1);
        #pragma unroll
        for (int ni = 0; ni < 8; ni++) {
            acc[mi][ni][0] *= i0; acc[mi][ni][1] *= i0;
            acc[mi][ni][2] *= i1; acc[mi][ni][3] *= i1;
        }
    }

    #pragma unroll
    for (int mi = 0; mi < 4; mi++) {
        size_t rA = r0 + wm + mi * 16 + group;
        #pragma unroll
        for (int ni = 0; ni < 8; ni++) {
            int c = n0 + wn + ni * 8 + t4 * 2;
            *(__half2*)&C[rA * HD + c] =
                __floats2half2_rn(acc[mi][ni][0], acc[mi][ni][1]);
            *(__half2*)&C[(rA + 8) * HD + c] =
                __floats2half2_rn(acc[mi][ni][2], acc[mi][ni][3]);
        }
    }

    if (which == 1) {
        float cs[8][2];
        #pragma unroll
        for (int ni = 0; ni < 8; ni++) {
            cs[ni][0] = 0.f; cs[ni][1] = 0.f;
            #pragma unroll
            for (int mi = 0; mi < 4; mi++) {
                cs[ni][0] += acc[mi][ni][0] + acc[mi][ni][2];
                cs[ni][1] += acc[mi][ni][1] + acc[mi][ni][3];
            }
            #pragma unroll
            for (int o = 4; o < 32; o <<= 1) {
                cs[ni][0] += __shfl_xor_sync(0xffffffffu, cs[ni][0], o);
                cs[ni][1] += __shfl_xor_sync(0xffffffffu, cs[ni][1], o);
            }
        }
        __syncthreads();
        float* cbuf = (float*)smc;
        if (lane < 4) {
            #pragma unroll
            for (int ni = 0; ni < 8; ni++) {
                cbuf[warp * 64 + ni * 8 + lane * 2]     = cs[ni][0];
                cbuf[warp * 64 + ni * 8 + lane * 2 + 1] = cs[ni][1];
            }
        }
        __syncthreads();
        int g2 = tid >> 6, cc = tid & 63;
        float s = cbuf[(2 * g2) * 64 + cc] + cbuf[(2 * g2 + 1) * 64 + cc];
        g_ksum_p2[blockIdx.y * HD + n0 + g2 * 64 + cc] = s;
    }
}

// ---------------- ksum final reduce ------------------------------------------
__global__ void ksum_red_kernel() {
    int c = blockIdx.x * 256 + threadIdx.x;   // grid.x = 4
    float s = 0.f;
    for (int p = 0; p < 512; p++) s += g_ksum_p2[p * HD + c];
    g_ksum[c] = s;
}

// ---------------- invden[n,h] = 1/(qn . ksum[h] + N) -------------------------
__global__ void invden_kernel() {
    int wg = blockIdx.x * 8 + (threadIdx.x >> 5);
    int lane = threadIdx.x & 31, h = wg & 3;
    size_t base = (size_t)wg * 256 + lane * 8;
    uint4 raw = *(const uint4*)&g_q[base];
    __half2* p = (__half2*)&raw;
    const float* ks = &g_ksum[h * 256 + lane * 8];
    float s = 0.f;
    #pragma unroll
    for (int i = 0; i < 4; i++) {
        float2 f = __half22float2(p[i]);
        s += f.x * ks[2 * i] + f.y * ks[2 * i + 1];
    }
    #pragma unroll
    for (int o = 16; o > 0; o >>= 1) s += __shfl_xor_sync(0xffffffffu, s, o);
    if (lane == 0) g_invden[wg] = 1.f / (s + 65536.f);
}

// ---------------- C = kn^T @ x : [1024, 512], 9-way split-K ------------------
#define CA_PITCH 136
#define CB_PITCH 264
#define CA_STG (64 * CA_PITCH)
#define CB_STG (64 * CB_PITCH)
#define C_SMEM_BYTES ((3 * (CA_STG + CB_STG)) * 2)
#define NCHUNK 9
#define STRIPS_PER_CHUNK 114   // 64-row strips; last chunk gets 112

__global__ __launch_bounds__(256) void c_kernel() {
    extern __shared__ __half sm[];
    __half* As = sm;
    __half* Bs = sm + 3 * CA_STG;

    int tid = threadIdx.x, lane = tid & 31, warp = tid >> 5;
    int wm = (warp & 1) * 64, wn = (warp >> 1) * 64;
    int m0 = blockIdx.x * 128;                   // grid.x = 8
    int j0 = blockIdx.y * 256;                   // grid.y = 2
    int chunk = blockIdx.z;                      // grid.z = 9
    int s0 = chunk * STRIPS_PER_CHUNK;
    int s1 = min(1024, s0 + STRIPS_PER_CHUNK);
    int L = s1 - s0;
    int quad = lane >> 3, r8 = lane & 7;
    int arow = tid >> 4, aseg = tid & 15;
    int brow = tid >> 5, bseg = tid & 31;

    float acc[4][8][4];
    #pragma unroll
    for (int a = 0; a < 4; a++)
        #pragma unroll
        for (int b = 0; b < 8; b++)
            #pragma unroll
            for (int c = 0; c < 4; c++) acc[a][b][c] = 0.f;

    auto load_stage = [&](int st, int strip) {
        size_t nb = (size_t)(s0 + strip) * 64;
        #pragma unroll
        for (int rr = 0; rr < 4; rr++)
            cp16(&As[st * CA_STG + (arow + rr * 16) * CA_PITCH + aseg * 8],
                 &g_k[(nb + arow + rr * 16) * HD + m0 + aseg * 8]);
        #pragma unroll
        for (int rr = 0; rr < 8; rr++)
            cp16(&Bs[st * CB_STG + (brow + rr * 8) * CB_PITCH + bseg * 8],
                 &g_xh[(nb + brow + rr * 8) * INC + j0 + bseg * 8]);
        cp_commit();
    };

    load_stage(0, 0);
    load_stage(1, 1);
    #pragma unroll 1
    for (int it = 0; it < L; it++) {
        int st = it % 3;
        if (it < L - 1) cp_wait<1>(); else cp_wait<0>();
        __syncthreads();
        if (it + 2 < L) load_stage((it + 2) % 3, it + 2);
        #pragma unroll
        for (int ks = 0; ks < 64; ks += 16) {
            uint32_t af[4][4], bf[4][4];
            #pragma unroll
            for (int mi = 0; mi < 4; mi++)
                ldsm4t(af[mi], smem_u32(&As[st * CA_STG +
                    (ks + (quad >> 1) * 8 + r8) * CA_PITCH + wm + mi * 16 + (quad & 1) * 8]));
            #pragma unroll
            for (int nj = 0; nj < 4; nj++)
                ldsm4t(bf[nj], smem_u32(&Bs[st * CB_STG +
                    (ks + (quad & 1) * 8 + r8) * CB_PITCH + wn + nj * 16 + (quad >> 1) * 8]));
            #pragma unroll
            for (int mi = 0; mi < 4; mi++)
                #pragma unroll
                for (int nj = 0; nj < 4; nj++) {
                    mma16816f(acc[mi][2 * nj],     af[mi], &bf[nj][0]);
                    mma16816f(acc[mi][2 * nj + 1], af[mi], &bf[nj][2]);
                }
        }
    }
    int group = lane >> 2, t4 = lane & 3;
    float* dst = &g_C_part[(size_t)chunk * (HD * INC)];
    #pragma unroll
    for (int mi = 0; mi < 4; mi++) {
        int rm = m0 + wm + mi * 16 + group;
        #pragma unroll
        for (int ni = 0; ni < 8; ni++) {
            int c = j0 + wn + ni * 8 + t4 * 2;
            *(float2*)&dst[rm * INC + c]       = make_float2(acc[mi][ni][0], acc[mi][ni][1]);
            *(float2*)&dst[(rm + 8) * INC + c] = make_float2(acc[mi][ni][2], acc[mi][ni][3]);
        }
    }
}

__global__ void cred_kernel() {
    int i = blockIdx.x * 256 + threadIdx.x;      // grid = 2048
    float s = 0.f;
    #pragma unroll
    for (int p = 0; p < NCHUNK; p++) s += g_C_part[(size_t)p * (HD * INC) + i];
    g_C[i] = __float2half(s);
}

// -------- kv_h = C_h @ Wv_h + ksum_h (x) bv_h : [4][256][256] -> f16 ---------
__global__ __launch_bounds__(256) void kvsmall_kernel(const float* __restrict__ bv) {
    __shared__ __half As[128][72];
    __shared__ __half Bs[64][136];
    int h = blockIdx.z;
    int m0 = blockIdx.x * 128;
    int d0 = blockIdx.y * 128;
    int tid = threadIdx.x, lane = tid & 31, warp = tid >> 5;
    int wm = (warp & 1) * 64, wn = (warp >> 1) * 32;
    int quad = lane >> 3, r8 = lane & 7;
    int arow = tid >> 3, aseg = tid & 7;
    int brow = tid >> 4, bseg = tid & 15;

    float acc[4][4][4];
    #pragma unroll
    for (int a = 0; a < 4; a++)
        #pragma unroll
        for (int b = 0; b < 4; b++)
            #pragma unroll
            for (int c = 0; c < 4; c++) acc[a][b][c] = 0.f;

    #pragma unroll 1
    for (int kt = 0; kt < 8; kt++) {
        int k0 = kt * 64;
        __syncthreads();
        #pragma unroll
        for (int rr = 0; rr < 4; rr++)
            *(uint4*)&As[arow + rr * 32][aseg * 8] =
                *(const uint4*)&g_C[(size_t)(h * 256 + m0 + arow + rr * 32) * INC + k0 + aseg * 8];
        #pragma unroll
        for (int rr = 0; rr < 4; rr++)
            *(uint4*)&Bs[brow + rr * 16][bseg * 8] =
                *(const uint4*)&g_wh[2][(size_t)(k0 + brow + rr * 16) * HD + h * 256 + d0 + bseg * 8];
        __syncthreads();
        #pragma unroll
        for (int ks = 0; ks < 64; ks += 16) {
            uint32_t af[4][4], bf[2][4];
            #pragma unroll
            for (int mi = 0; mi < 4; mi++)
                ldsm4(af[mi], smem_u32(&As[wm + mi * 16 + (quad & 1) * 8 + r8][ks + (quad >> 1) * 8]));
            #pragma unroll
            for (int nj = 0; nj < 2; nj++)
                ldsm4t(bf[nj], smem_u32(&Bs[ks + (quad & 1) * 8 + r8][wn + nj * 16 + (quad >> 1) * 8]));
            #pragma unroll
            for (int mi = 0; mi < 4; mi++)
                #pragma unroll
                for (int nj = 0; nj < 2; nj++) {
                    mma16816f(acc[mi][2 * nj],     af[mi], &bf[nj][0]);
                    mma16816f(acc[mi][2 * nj + 1], af[mi], &bf[nj][2]);
                }
        }
    }

    int group = lane >> 2, t4 = lane & 3;
    #pragma unroll
    for (int mi = 0; mi < 4; mi++) {
        int rm = m0 + wm + mi * 16 + group;
        float ksA = g_ksum[h * 256 + rm], ksB = g_ksum[h * 256 + rm + 8];
        #pragma unroll
        for (int ni = 0; ni < 4; ni++) {
            int c = d0 + wn + ni * 8 + t4 * 2;
            float b0 = __ldg(&bv[h * 256 + c]), b1 = __ldg(&bv[h * 256 + c + 1]);
            *(__half2*)&g_kvb[(size_t)(h * 256 + rm) * 256 + c] =
                __floats2half2_rn(acc[mi][ni][0] + ksA * b0, acc[mi][ni][1] + ksA * b1);
            *(__half2*)&g_kvb[(size_t)(h * 256 + rm + 8) * 256 + c] =
                __floats2half2_rn(acc[mi][ni][2] + ksB * b0, acc[mi][ni][3] + ksB * b1);
        }
    }
}

// ------ out = 0.25*((q*invden*65536) @ kv / 65536 + rowoff), K=1024 ----------
#define OAPITCH 72
#define OASTG (128 * OAPITCH)
#define OBSTG (64 * BPITCH)
#define OUT_SMEM_BYTES ((3 * (OASTG + OBSTG)) * 2)

__global__ __launch_bounds__(512) void out_kernel(float* __restrict__ out) {
    extern __shared__ __half sm[];
    __half* As = sm;
    __half* Bs = sm + 3 * OASTG;

    size_t r0 = (size_t)blockIdx.y * 128;
    int tid = threadIdx.x, lane = tid & 31, warp = tid >> 5;
    int wm = (warp & 3) * 32, wn = (warp >> 2) * 64;
    int quad = lane >> 3, r8 = lane & 7;
    int arow = tid >> 3, aseg = tid & 7;
    int brow = tid >> 5, bseg = tid & 31;

    float acc[2][8][4];
    #pragma unroll
    for (int a = 0; a < 2; a++)
        #pragma unroll
        for (int b = 0; b < 8; b++)
            #pragma unroll
            for (int c = 0; c < 4; c++) acc[a][b][c] = 0.f;

    uint4 aR[2];
    float invR[2];

    auto ldgA = [&](int kit) {
        int k0 = kit * 64, h = k0 >> 8;
        #pragma unroll
        for (int rr = 0; rr < 2; rr++) {
            size_t row = r0 + arow + rr * 64;
            aR[rr] = *(const uint4*)&g_q[row * HD + k0 + aseg * 8];
            invR[rr] = g_invden[row * 4 + h];
        }
    };
    auto stsA = [&](int kit) {
        int st = kit % 3;
        #pragma unroll
        for (int rr = 0; rr < 2; rr++) {
            __half2* p = (__half2*)&aR[rr];
            float iv = invR[rr] * 65536.f;
            uint4 o;
            __half2* q = (__half2*)&o;
            #pragma unroll
            for (int j = 0; j < 4; j++) {
                float2 f = __half22float2(p[j]);
                q[j] = __floats2half2_rn(f.x * iv, f.y * iv);
            }
            *(uint4*)&As[st * OASTG + (arow + rr * 64) * OAPITCH + aseg * 8] = o;
        }
    };
    auto cpB = [&](int kit) {
        int st = kit % 3, k0 = kit * 64;
        #pragma unroll
        for (int rr = 0; rr < 4; rr++)
            cp16(&Bs[st * OBSTG + (brow + rr * 16) * BPITCH + bseg * 8],
                 &g_kvb[(size_t)(k0 + brow + rr * 16) * 256 + bseg * 8]);
        cp_commit();
    };

    ldgA(0); stsA(0);
    ldgA(1);
    cpB(0); cpB(1);
    #pragma unroll 1
    for (int it = 0; it < 16; it++) {
        int st = it % 3;
        if (it < 15) cp_wait<1>(); else cp_wait<0>();
        __syncthreads();
        if (it + 1 < 16) stsA(it + 1);
        if (it + 2 < 16) { ldgA(it + 2); cpB(it + 2); }
        #pragma unroll
        for (int ks = 0; ks < 64; ks += 16) {
            uint32_t af[2][4], bf[4][4];
            #pragma unroll
            for (int mi = 0; mi < 2; mi++)
                ldsm4(af[mi], smem_u32(&As[st * OASTG +
                    (wm + mi * 16 + (quad & 1) * 8 + r8) * OAPITCH + ks + (quad >> 1) * 8]));
            #pragma unroll
            for (int nj = 0; nj < 4; nj++)
                ldsm4t(bf[nj], smem_u32(&Bs[st * OBSTG +
                    (ks + (quad & 1) * 8 + r8) * BPITCH + wn + nj * 16 + (quad >> 1) * 8]));
            #pragma unroll
            for (int mi = 0; mi < 2; mi++)
                #pragma unroll
                for (int nj = 0; nj < 4; nj++) {
                    mma16816f(acc[mi][2 * nj],     af[mi], &bf[nj][0]);
                    mma16816f(acc[mi][2 * nj + 1], af[mi], &bf[nj][2]);
                }
        }
    }

    const float inv64k = 1.f / 65536.f;
    int group = lane >> 2, t4 = lane & 3;
    #pragma unroll
    for (int mi = 0; mi < 2; mi++) {
        size_t rA = r0 + wm + mi * 16 + group;
        size_t rB = rA + 8;
        float ia[4], ib[4];
        #pragma unroll
        for (int h = 0; h < 4; h++) {
            ia[h] = g_invden[rA * 4 + h];
            ib[h] = g_invden[rB * 4 + h];
        }
        #pragma unroll
        for (int ni = 0; ni < 8; ni++) {
            int c = wn + ni * 8 + t4 * 2;
            float roa0 = 0.f, roa1 = 0.f, rob0 = 0.f, rob1 = 0.f;
            #pragma unroll
            for (int h = 0; h < 4; h++) {
                float v0 = __ldg(&g_vsum[h * 256 + c]);
                float v1 = __ldg(&g_vsum[h * 256 + c + 1]);
                roa0 += ia[h] * v0; roa1 += ia[h] * v1;
                rob0 += ib[h] * v0; rob1 += ib[h] * v1;
            }
            *(float2*)&out[rA * 256 + c] =
                make_float2(0.25f * (acc[mi][ni][0] * inv64k + roa0),
                            0.25f * (acc[mi][ni][1] * inv64k + roa1));
            *(float2*)&out[rB * 256 + c] =
                make_float2(0.25f * (acc[mi][ni][2] * inv64k + rob0),
                            0.25f * (acc[mi][ni][3] * inv64k + rob1));
        }
    }
}

// ---------------- launch (fork/join streams, capture-safe) -------------------
extern "C" void kernel_launch(void* const* d_in, const int* in_sizes, int n_in,
                              void* d_out, int out_size) {
    const float* x  = (const float*)d_in[0];
    const float* Wq = (const float*)d_in[1];
    const float* bq = (const float*)d_in[2];
    const float* Wk = (const float*)d_in[3];
    const float* bk = (const float*)d_in[4];
    const float* Wv = (const float*)d_in[5];
    const float* bv = (const float*)d_in[6];
    float* out = (float*)d_out;

    cudaFuncSetAttribute(qk_kernel,  cudaFuncAttributeMaxDynamicSharedMemorySize, GEMM_SMEM_BYTES);
    cudaFuncSetAttribute(c_kernel,   cudaFuncAttributeMaxDynamicSharedMemorySize, C_SMEM_BYTES);
    cudaFuncSetAttribute(out_kernel, cudaFuncAttributeMaxDynamicSharedMemorySize, OUT_SMEM_BYTES);

    cudaStream_t s1;
    cudaStreamCreateWithFlags(&s1, cudaStreamNonBlocking);
    cudaEvent_t evX, evQK, evSide;
    cudaEventCreateWithFlags(&evX, cudaEventDisableTiming);
    cudaEventCreateWithFlags(&evQK, cudaEventDisableTiming);
    cudaEventCreateWithFlags(&evSide, cudaEventDisableTiming);

    // main stream: the roofline chain
    cvt_x_kernel<<<256, 256>>>(x);
    cudaEventRecord(evX, 0);
    cvt_w_kernel<<<dim3(512, 3), 256>>>(Wq, Wk, Wv);
    qk_kernel<<<dim3(8, 512), 256, GEMM_SMEM_BYTES>>>(bq, bk);
    cudaEventRecord(evQK, 0);

    // side stream: colsum/vsum after cvt_x; ksum/invden after qk
    cudaStreamWaitEvent(s1, evX, 0);
    colsum_red_kernel<<<2, 256, 0, s1>>>();
    vsum_kernel<<<128, 256, 0, s1>>>(Wv, bv);
    cudaStreamWaitEvent(s1, evQK, 0);
    ksum_red_kernel<<<4, 256, 0, s1>>>();
    invden_kernel<<<32768, 256, 0, s1>>>();
    cudaEventRecord(evSide, s1);

    // main continues: C (overlaps side work), then join before kvsmall/out
    c_kernel<<<dim3(8, 2, NCHUNK), 256, C_SMEM_BYTES>>>();
    cred_kernel<<<2048, 256>>>();
    cudaStreamWaitEvent(0, evSide, 0);
    kvsmall_kernel<<<dim3(2, 2, 4), 256>>>(bv);
    out_kernel<<<dim3(1, 512), 512, OUT_SMEM_BYTES>>>(out);
}